// round 7
// baseline (speedup 1.0000x reference)
#include <cuda_runtime.h>
#include <cuda_bf16.h>

// ---------------- problem constants ----------------
#define BATCH 256
#define FRAMES 256
#define IN_DIM 34
#define NJ3 51
#define DDIM 512
#define G4 2048            // 4*D
#define K0 608             // 34 (x) + 51 (pred) + 512 (h0) padded 597->608
#define K1 1024            // 512 (h0n) + 512 (h1prev)
#define GRID 128
#define THREADS 256
#define NT (GRID*THREADS)

typedef unsigned long long u64;

// packed f32x2 FMA (sm_103a FFMA2; only reachable via PTX)
#define FMA2(d, a, b) asm("fma.rn.f32x2 %0, %1, %2, %0;" : "+l"(d) : "l"(a), "l"(b))
#define UNPACK2(lo, hi, p) asm("mov.b64 {%0, %1}, %2;" : "=f"(lo), "=f"(hi) : "l"(p))

// smem geometry for the fused GEMM (floats)
#define AS_STRIDE 140              // 64 m duplicated (128) + pad -> 16B-aligned rows
#define AS_BUF (16*AS_STRIDE)      // 2240
#define BS_BUF (16*64)             // 1024
#define SM_TOTAL (2*AS_BUF + 2*BS_BUF)   // 6528 floats = 26.1 KB

// ---------------- device scratch ----------------
// Gate-interleaved weights: column m' = 4*d + gate   (gate: 0=i,1=f,2=g,3=o)
__device__ float g_W0t[K0*G4];
__device__ float g_W1t[K1*G4];
__device__ float g_bias0[G4];
__device__ float g_bias1[G4];
__device__ float g_initp[BATCH*96];
__device__ float g_niW1p[96*DDIM];
__device__ float g_z1[BATCH*DDIM];
__device__ float g_z2[BATCH*1024];
__device__ float g_z3[BATCH*2048];
// Ping-pong activation buffers (race-free with fused epilogues)
__device__ float g_X0[2][BATCH*K0];   // [b][k]: 0..33 x_t, 34..84 pred, 85..596 h0, pad
__device__ float g_X1[2][BATCH*K1];   // [b][k]: 0..511 h0n(this step), 512..1023 h1(prev)
__device__ float g_c0[BATCH*DDIM];
__device__ float g_c1[BATCH*DDIM];

// barrier state
__device__ unsigned int g_arrive;
__device__ volatile unsigned int g_release;

__device__ __forceinline__ void grid_sync() {
    __threadfence();
    __syncthreads();
    if (threadIdx.x == 0) {
        unsigned int gen = g_release;
        unsigned int prev = atomicAdd(&g_arrive, 1u);
        if (prev == gridDim.x - 1u) {
            g_arrive = 0u;
            __threadfence();
            g_release = gen + 1u;
        } else {
            while (g_release == gen) { __nanosleep(32); }
        }
        __threadfence();
    }
    __syncthreads();
}

__device__ __forceinline__ float sigf(float v)  { return 1.0f / (1.0f + __expf(-v)); }
__device__ __forceinline__ float tanhg(float v) { float e = __expf(2.0f*v); return 1.0f - 2.0f/(e + 1.0f); }

// ---------------- setup kernel 1: folded x-weight + bias0 (interleaved) ----------------
__global__ void k_setup_heavy(const float* __restrict__ embed_W,
                              const float* __restrict__ embed_b,
                              const float* __restrict__ Wih0,
                              const float* __restrict__ bih0,
                              const float* __restrict__ bhh0) {
    int idx = blockIdx.x * blockDim.x + threadIdx.x;
    const int TOT = 34*G4 + G4;
    for (; idx < TOT; idx += gridDim.x * blockDim.x) {
        if (idx < 34*G4) {
            int m = idx & 2047, j = idx >> 11;
            int mp = ((m & 511) << 2) | (m >> 9);        // interleave
            const float* wr = Wih0 + m*563;
            const float* er = embed_W + j*512;
            float s = 0.f;
            #pragma unroll 4
            for (int d = 0; d < 512; d++) s += er[d] * wr[d];
            g_W0t[j*G4 + mp] = s;
        } else {
            int m = idx - 34*G4;
            int mp = ((m & 511) << 2) | (m >> 9);
            const float* wr = Wih0 + m*563;
            float s = bih0[m] + bhh0[m];
            #pragma unroll 4
            for (int d = 0; d < 512; d++) s += embed_b[d] * wr[d];
            g_bias0[mp] = s;
        }
    }
}

// ---------------- setup kernel 2: packs/copies (interleaved weights) ----------------
__global__ void k_setup_copy(const float* __restrict__ x,
                             const float* __restrict__ init,
                             const float* __restrict__ Wih0,
                             const float* __restrict__ Whh0,
                             const float* __restrict__ Wih1,
                             const float* __restrict__ Whh1,
                             const float* __restrict__ bih1,
                             const float* __restrict__ bhh1,
                             const float* __restrict__ niW1) {
    const int S1 = 574*G4;            // W0t rows 34..607
    const int S2 = 1024*G4;           // W1t
    const int S3 = G4;                // bias1
    const int S4 = BATCH*96;          // initp
    const int S5 = 96*DDIM;           // niW1p
    const int S6 = BATCH*85;          // X0[0] cols 0..84 (x_0 | pred0)
    const int S7 = BATCH*22;          // X0 pad cols 597..607, both buffers
    const int TOT = S1+S2+S3+S4+S5+S6+S7;
    int i = blockIdx.x * blockDim.x + threadIdx.x;
    for (; i < TOT; i += gridDim.x * blockDim.x) {
        int r = i;
        if (r < S1) {
            int m = r & 2047; int k = 34 + (r >> 11);
            int mp = ((m & 511) << 2) | (m >> 9);
            float v;
            if (k < 85)       v = Wih0[m*563 + 512 + (k-34)];
            else if (k < 597) v = Whh0[m*512 + (k-85)];
            else              v = 0.f;
            g_W0t[k*G4 + mp] = v;
            continue;
        }
        r -= S1;
        if (r < S2) {
            int m = r & 2047; int k = r >> 11;
            int mp = ((m & 511) << 2) | (m >> 9);
            g_W1t[k*G4 + mp] = (k < 512) ? Wih1[m*512 + k] : Whh1[m*512 + (k-512)];
            continue;
        }
        r -= S2;
        if (r < S3) {
            int mp = ((r & 511) << 2) | (r >> 9);
            g_bias1[mp] = bih1[r] + bhh1[r]; continue;
        }
        r -= S3;
        if (r < S4) { int b = r/96, j = r - b*96; g_initp[r] = (j < 85) ? init[b*85 + j] : 0.f; continue; }
        r -= S4;
        if (r < S5) { int k = r >> 9;  g_niW1p[r] = (k < 85) ? niW1[r] : 0.f; continue; }
        r -= S5;
        if (r < S6) {
            int b = r/85, j = r - b*85;
            g_X0[0][b*K0 + j] = (j < 34) ? x[(b*FRAMES)*IN_DIM + j] : init[b*85 + (j-34)];
            continue;
        }
        r -= S6;
        { int b = r/22, jj = r - b*22; g_X0[jj/11][b*K0 + 597 + (jj%11)] = 0.f; }
    }
}

// ---------------- generic tiled GEMM (init MLP only; scalar path, runs once) -----------
template<bool RELU>
__device__ __forceinline__ void gemm_nt(const float* __restrict__ A, int lda,
                                        const float* __restrict__ B, int ldb,
                                        float* __restrict__ C, int ldc,
                                        int M, int N, int K,
                                        const float* __restrict__ bias,
                                        float* sm) {
    float* As = sm;             // [16][68]
    float* Bs = sm + 16*68;     // [16][64]
    const int tid = threadIdx.x;
    const int nT = N >> 6;
    const int ntiles = (M >> 6) * nT;
    const int ar = tid >> 2, ac = (tid & 3) << 2;
    const int bk = tid >> 4, bn = (tid & 15) << 2;
    const int ty = tid >> 4, tx = tid & 15;
    for (int tile = blockIdx.x; tile < ntiles; tile += gridDim.x) {
        const int m0 = (tile / nT) << 6;
        const int n0 = (tile - (tile / nT) * nT) << 6;
        float4 acc0 = make_float4(0,0,0,0), acc1 = acc0, acc2 = acc0, acc3 = acc0;
        for (int k0 = 0; k0 < K; k0 += 16) {
            float4 va = __ldcg((const float4*)(A + (m0 + ar)*lda + k0 + ac));
            float4 vb = __ldg ((const float4*)(B + (k0 + bk)*ldb + n0 + bn));
            As[(ac+0)*68 + ar] = va.x;
            As[(ac+1)*68 + ar] = va.y;
            As[(ac+2)*68 + ar] = va.z;
            As[(ac+3)*68 + ar] = va.w;
            *(float4*)(Bs + bk*64 + bn) = vb;
            __syncthreads();
            #pragma unroll
            for (int kk = 0; kk < 16; kk++) {
                float4 a = *(const float4*)(As + kk*68 + (ty << 2));
                float4 b = *(const float4*)(Bs + kk*64 + (tx << 2));
                acc0.x += a.x*b.x; acc0.y += a.x*b.y; acc0.z += a.x*b.z; acc0.w += a.x*b.w;
                acc1.x += a.y*b.x; acc1.y += a.y*b.y; acc1.z += a.y*b.z; acc1.w += a.y*b.w;
                acc2.x += a.z*b.x; acc2.y += a.z*b.y; acc2.z += a.z*b.z; acc2.w += a.z*b.w;
                acc3.x += a.w*b.x; acc3.y += a.w*b.y; acc3.z += a.w*b.z; acc3.w += a.w*b.w;
            }
            __syncthreads();
        }
        float4 bb = __ldg((const float4*)(bias + n0 + (tx << 2)));
        float4 accs[4] = {acc0, acc1, acc2, acc3};
        #pragma unroll
        for (int i = 0; i < 4; i++) {
            float4 v = accs[i];
            v.x += bb.x; v.y += bb.y; v.z += bb.z; v.w += bb.w;
            if (RELU) { v.x = fmaxf(v.x, 0.f); v.y = fmaxf(v.y, 0.f);
                        v.z = fmaxf(v.z, 0.f); v.w = fmaxf(v.w, 0.f); }
            __stcg((float4*)(C + (m0 + (ty << 2) + i)*ldc + n0 + (tx << 2)), v);
        }
    }
}

// ---------------- fused GEMM (FFMA2) + LSTM-cell epilogue ----------------
// 64x64 tile per CTA (blockIdx.x = tile id; 128 tiles). A-tile staged DUPLICATED in smem
// (As[k][2m]=As[k][2m+1]=a) so each LDS.128 yields two (a,a) f32x2 operands.
// acc pairs map to (i,f) and (g,o) of one hidden unit d (gate-interleaved weights).
template<int LAYER>
__device__ __forceinline__ void gemm_cell(const float* __restrict__ A, int lda, int K,
                                          const float* __restrict__ W,
                                          const float* __restrict__ bias,
                                          float* __restrict__ cArr,
                                          float* __restrict__ X0next,
                                          float* __restrict__ X1cur,
                                          float* __restrict__ X1next,
                                          float* __restrict__ out_mc, int t,
                                          float* sm) {
    const int tid = threadIdx.x;
    const int tile = blockIdx.x;              // 128 tiles (4 m x 32 n)
    const int m0 = (tile >> 5) << 6;
    const int n0 = (tile & 31) << 6;
    const int ar = tid >> 2, ac = (tid & 3) << 2;
    const int bk = tid >> 4, bn = (tid & 15) << 2;
    const int ty = tid >> 4, tx = tid & 15;

    u64 acc[8] = {0ull,0ull,0ull,0ull,0ull,0ull,0ull,0ull};

    // prologue: k-tile 0 into buffer 0
    float4 va = __ldcg((const float4*)(A + (m0 + ar)*lda + ac));
    float4 vb = __ldg ((const float4*)(W + bk*G4 + n0 + bn));
    {
        float* As0 = sm;
        float* Bs0 = sm + 2*AS_BUF;
        *(float2*)(As0 + (ac+0)*AS_STRIDE + 2*ar) = make_float2(va.x, va.x);
        *(float2*)(As0 + (ac+1)*AS_STRIDE + 2*ar) = make_float2(va.y, va.y);
        *(float2*)(As0 + (ac+2)*AS_STRIDE + 2*ar) = make_float2(va.z, va.z);
        *(float2*)(As0 + (ac+3)*AS_STRIDE + 2*ar) = make_float2(va.w, va.w);
        *(float4*)(Bs0 + bk*64 + bn) = vb;
    }
    __syncthreads();

    int p = 0;
    for (int k0 = 0; k0 < K; k0 += 16) {
        const bool pre = (k0 + 16 < K);
        if (pre) {
            va = __ldcg((const float4*)(A + (m0 + ar)*lda + (k0 + 16) + ac));
            vb = __ldg ((const float4*)(W + (k0 + 16 + bk)*G4 + n0 + bn));
        }
        const float* Asp = sm + p*AS_BUF;
        const float* Bsp = sm + 2*AS_BUF + p*BS_BUF;
        #pragma unroll
        for (int kk = 0; kk < 16; kk++) {
            ulonglong2 a01 = *(const ulonglong2*)(Asp + kk*AS_STRIDE + (ty << 3));
            ulonglong2 a23 = *(const ulonglong2*)(Asp + kk*AS_STRIDE + (ty << 3) + 4);
            ulonglong2 b   = *(const ulonglong2*)(Bsp + kk*64 + (tx << 2));
            FMA2(acc[0], a01.x, b.x); FMA2(acc[1], a01.x, b.y);
            FMA2(acc[2], a01.y, b.x); FMA2(acc[3], a01.y, b.y);
            FMA2(acc[4], a23.x, b.x); FMA2(acc[5], a23.x, b.y);
            FMA2(acc[6], a23.y, b.x); FMA2(acc[7], a23.y, b.y);
        }
        if (pre) {
            float* Asn = sm + (p^1)*AS_BUF;
            float* Bsn = sm + 2*AS_BUF + (p^1)*BS_BUF;
            *(float2*)(Asn + (ac+0)*AS_STRIDE + 2*ar) = make_float2(va.x, va.x);
            *(float2*)(Asn + (ac+1)*AS_STRIDE + 2*ar) = make_float2(va.y, va.y);
            *(float2*)(Asn + (ac+2)*AS_STRIDE + 2*ar) = make_float2(va.z, va.z);
            *(float2*)(Asn + (ac+3)*AS_STRIDE + 2*ar) = make_float2(va.w, va.w);
            *(float4*)(Bsn + bk*64 + bn) = vb;
        }
        __syncthreads();
        p ^= 1;
    }

    // epilogue: LSTM cell on (i,f,g,o) quads
    float4 bb = __ldg((const float4*)(bias + n0 + (tx << 2)));
    const int dd = (n0 >> 2) + tx;            // hidden index for this thread's quad
    #pragma unroll
    for (int i = 0; i < 4; i++) {
        const int b = m0 + (ty << 2) + i;
        float vi, vf, vg, vo;
        UNPACK2(vi, vf, acc[2*i]);
        UNPACK2(vg, vo, acc[2*i + 1]);
        float ig = sigf (vi + bb.x);
        float fg = sigf (vf + bb.y);
        float gg = tanhg(vg + bb.z);
        float og = sigf (vo + bb.w);
        float c  = fg * cArr[b*DDIM + dd] + ig * gg;   // c: CTA-private across steps
        cArr[b*DDIM + dd] = c;
        float h = og * tanhg(c);
        if (LAYER == 0) {
            __stcg(&X1cur [b*K1 + dd], h);             // input to gates1 (this step)
            __stcg(&X0next[b*K0 + 85 + dd], h);        // recurrent h0 (next step)
        } else {
            __stcg(&X1next[b*K1 + 512 + dd], h);       // recurrent h1 (next step)
            out_mc[((long)b*FRAMES + t)*563 + dd] = h; // motion_context h part
        }
    }
}

// ---------------- persistent scan kernel ----------------
__global__ void __launch_bounds__(THREADS, 1)
k_persist(const float* __restrict__ x,
          const float* __restrict__ niW2, const float* __restrict__ niW3,
          const float* __restrict__ nb1,  const float* __restrict__ nb2,
          const float* __restrict__ nb3,
          const float* __restrict__ decW, const float* __restrict__ decb,
          float* __restrict__ out_pred, float* __restrict__ out_mc) {
    __shared__ float sm[SM_TOTAL];
    const int gtid = blockIdx.x * THREADS + threadIdx.x;

    // ---- init network ----
    gemm_nt<true >(g_initp, 96,   g_niW1p, DDIM, g_z1, DDIM, BATCH, DDIM, 96,   nb1, sm);
    grid_sync();
    gemm_nt<true >(g_z1,   DDIM,  niW2,    1024, g_z2, 1024, BATCH, 1024, DDIM, nb2, sm);
    grid_sync();
    gemm_nt<false>(g_z2,   1024,  niW3,    2048, g_z3, 2048, BATCH, 2048, 1024, nb3, sm);
    grid_sync();
    for (int idx = gtid; idx < BATCH*DDIM; idx += NT) {
        int b = idx >> 9, d = idx & 511;
        const float* zr = g_z3 + b*2048;
        __stcg(&g_X0[0][b*K0 + 85 + d],  __ldcg(zr + d));          // h0 init
        __stcg(&g_X1[0][b*K1 + 512 + d], __ldcg(zr + 512 + d));    // h1 init
        __stcg(&g_c0[idx],               __ldcg(zr + 1024 + d));
        __stcg(&g_c1[idx],               __ldcg(zr + 1536 + d));
    }
    grid_sync();

    // ---- scan: 3 grid syncs per step ----
    for (int t = 0; t < FRAMES; t++) {
        const int cur = t & 1, nxt = cur ^ 1;

        // phase A: gates0 GEMM + cell0 epilogue
        gemm_cell<0>(g_X0[cur], K0, K0, g_W0t, g_bias0, g_c0,
                     g_X0[nxt], g_X1[cur], nullptr, nullptr, t, sm);
        grid_sync();

        // phase B: gates1 GEMM + cell1 epilogue
        gemm_cell<1>(g_X1[cur], K1, K1, g_W1t, g_bias1, g_c1,
                     nullptr, nullptr, g_X1[nxt], out_mc, t, sm);
        grid_sync();

        // phase C: decoder + next-step x copy (block -> 2 batch rows)
        {
            float* h1s = sm;                     // reuse smem (1024 floats)
            const int b0 = blockIdx.x << 1;
            for (int i = threadIdx.x; i < 1024; i += THREADS) {
                int bb = i >> 9, d = i & 511;
                h1s[i] = __ldcg(&g_X1[nxt][(b0 + bb)*K1 + 512 + d]);
            }
            __syncthreads();
            int bb = threadIdx.x >> 7, jj = threadIdx.x & 127;
            if (jj < NJ3) {
                int b = b0 + bb;
                float s = __ldg(&decb[jj]);
                const float* hr = h1s + (bb << 9);
                #pragma unroll 8
                for (int d = 0; d < 512; d++) s += hr[d] * __ldg(&decW[d*NJ3 + jj]);
                long bt = (long)b*FRAMES + t;
                out_pred[bt*NJ3 + jj] = s;
                out_mc[bt*563 + 512 + jj] = s;
                __stcg(&g_X0[nxt][b*K0 + 34 + jj], s);
            }
            if (t + 1 < FRAMES) {
                for (int i = threadIdx.x; i < 2*IN_DIM; i += THREADS) {
                    int bb2 = i / IN_DIM, j = i - bb2*IN_DIM;
                    int b = b0 + bb2;
                    __stcg(&g_X0[nxt][b*K0 + j], x[((long)b*FRAMES + t + 1)*IN_DIM + j]);
                }
            }
        }
        grid_sync();
    }
}

// ---------------- entry ----------------
extern "C" void kernel_launch(void* const* d_in, const int* in_sizes, int n_in,
                              void* d_out, int out_size) {
    const float* x       = (const float*)d_in[0];
    const float* init_   = (const float*)d_in[1];
    const float* embed_W = (const float*)d_in[2];
    const float* embed_b = (const float*)d_in[3];
    const float* ni_W1   = (const float*)d_in[4];
    const float* ni_b1   = (const float*)d_in[5];
    const float* ni_W2   = (const float*)d_in[6];
    const float* ni_b2   = (const float*)d_in[7];
    const float* ni_W3   = (const float*)d_in[8];
    const float* ni_b3   = (const float*)d_in[9];
    const float* Wih0    = (const float*)d_in[10];
    const float* Whh0    = (const float*)d_in[11];
    const float* bih0    = (const float*)d_in[12];
    const float* bhh0    = (const float*)d_in[13];
    const float* Wih1    = (const float*)d_in[14];
    const float* Whh1    = (const float*)d_in[15];
    const float* bih1    = (const float*)d_in[16];
    const float* bhh1    = (const float*)d_in[17];
    const float* dec_W   = (const float*)d_in[18];
    const float* dec_b   = (const float*)d_in[19];

    float* out_pred = (float*)d_out;                              // (256,256,17,3)
    float* out_mc   = out_pred + (long)BATCH*FRAMES*NJ3;          // (256,256,563)

    k_setup_heavy<<<280, 256>>>(embed_W, embed_b, Wih0, bih0, bhh0);
    k_setup_copy <<<2048, 256>>>(x, init_, Wih0, Whh0, Wih1, Whh1, bih1, bhh1, ni_W1);
    k_persist    <<<GRID, THREADS>>>(x, ni_W2, ni_W3, ni_b1, ni_b2, ni_b3,
                                     dec_W, dec_b, out_pred, out_mc);
}

// round 8
// speedup vs baseline: 1.4501x; 1.4501x over previous
#include <cuda_runtime.h>
#include <cuda_bf16.h>

// ---------------- problem constants ----------------
#define BATCH 256
#define FRAMES 256
#define IN_DIM 34
#define NJ3 51
#define DDIM 512
#define G4 2048            // 4*D
#define K0 608             // 34 (x) + 51 (pred) + 512 (h0) padded 597->608
#define K1 1024            // 512 (h0n) + 512 (h1prev)
#define GRID 128
#define THREADS 256
#define NT (GRID*THREADS)

typedef unsigned short ushort_t;

// ---------------- PTX helpers ----------------
#define LDSM4(R, addr) asm volatile( \
    "ldmatrix.sync.aligned.m8n8.x4.shared.b16 {%0,%1,%2,%3},[%4];" \
    : "=r"((R)[0]),"=r"((R)[1]),"=r"((R)[2]),"=r"((R)[3]) : "r"(addr))
#define LDSM4T(R, addr) asm volatile( \
    "ldmatrix.sync.aligned.m8n8.x4.trans.shared.b16 {%0,%1,%2,%3},[%4];" \
    : "=r"((R)[0]),"=r"((R)[1]),"=r"((R)[2]),"=r"((R)[3]) : "r"(addr))
#define MMA_BF16(D, A, b0, b1) asm volatile( \
    "mma.sync.aligned.m16n8k16.row.col.f32.bf16.bf16.f32 " \
    "{%0,%1,%2,%3},{%4,%5,%6,%7},{%8,%9},{%0,%1,%2,%3};" \
    : "+f"((D)[0]),"+f"((D)[1]),"+f"((D)[2]),"+f"((D)[3]) \
    : "r"((A)[0]),"r"((A)[1]),"r"((A)[2]),"r"((A)[3]),"r"(b0),"r"(b1))

__device__ __forceinline__ void st_cg_u16(ushort_t* p, ushort_t v) {
    asm volatile("st.global.cg.u16 [%0], %1;" :: "l"(p), "h"(v));
}
__device__ __forceinline__ ushort_t ld_cg_u16(const ushort_t* p) {
    ushort_t v; asm volatile("ld.global.cg.u16 %0, [%1];" : "=h"(v) : "l"(p)); return v;
}
__device__ __forceinline__ void bsplit(float v, ushort_t& hi, ushort_t& lo) {
    __nv_bfloat16 h = __float2bfloat16(v);
    __nv_bfloat16 l2 = __float2bfloat16(v - __bfloat162float(h));
    hi = *(ushort_t*)&h; lo = *(ushort_t*)&l2;
}
__device__ __forceinline__ float bjoin(ushort_t hi, ushort_t lo) {
    __nv_bfloat16 h = *(__nv_bfloat16*)&hi, l2 = *(__nv_bfloat16*)&lo;
    return __bfloat162float(h) + __bfloat162float(l2);
}

// ---------------- device scratch ----------------
// Gate-interleaved weights, split bf16: column m' = 4*d + gate (0=i,1=f,2=g,3=o)
__device__ ushort_t g_W0h[K0*G4];
__device__ ushort_t g_W0l[K0*G4];
__device__ ushort_t g_W1h[K1*G4];
__device__ ushort_t g_W1l[K1*G4];
__device__ float g_bias0[G4];
__device__ float g_bias1[G4];
__device__ float g_initp[BATCH*96];
__device__ float g_niW1p[96*DDIM];
__device__ float g_z1[BATCH*DDIM];
__device__ float g_z2[BATCH*1024];
__device__ float g_z3[BATCH*2048];
// Ping-pong activations, split bf16
__device__ ushort_t g_X0h[2][BATCH*K0];
__device__ ushort_t g_X0l[2][BATCH*K0];
__device__ ushort_t g_X1h[2][BATCH*K1];
__device__ ushort_t g_X1l[2][BATCH*K1];
__device__ float g_c0[BATCH*DDIM];
__device__ float g_c1[BATCH*DDIM];

// barrier state
__device__ unsigned int g_arrive;
__device__ volatile unsigned int g_release;

__device__ __forceinline__ void grid_sync() {
    __threadfence();
    __syncthreads();
    if (threadIdx.x == 0) {
        unsigned int gen = g_release;
        unsigned int prev = atomicAdd(&g_arrive, 1u);
        if (prev == gridDim.x - 1u) {
            g_arrive = 0u;
            __threadfence();
            g_release = gen + 1u;
        } else {
            while (g_release == gen) { __nanosleep(32); }
        }
        __threadfence();
    }
    __syncthreads();
}

__device__ __forceinline__ float sigf(float v)  { return 1.0f / (1.0f + __expf(-v)); }
__device__ __forceinline__ float tanhg(float v) { float e = __expf(2.0f*v); return 1.0f - 2.0f/(e + 1.0f); }

// ---------------- setup kernel 1: folded x-weight + bias0 ----------------
__global__ void k_setup_heavy(const float* __restrict__ embed_W,
                              const float* __restrict__ embed_b,
                              const float* __restrict__ Wih0,
                              const float* __restrict__ bih0,
                              const float* __restrict__ bhh0) {
    int idx = blockIdx.x * blockDim.x + threadIdx.x;
    const int TOT = 34*G4 + G4;
    for (; idx < TOT; idx += gridDim.x * blockDim.x) {
        if (idx < 34*G4) {
            int m = idx & 2047, j = idx >> 11;
            int mp = ((m & 511) << 2) | (m >> 9);
            const float* wr = Wih0 + m*563;
            const float* er = embed_W + j*512;
            float s = 0.f;
            #pragma unroll 4
            for (int d = 0; d < 512; d++) s += er[d] * wr[d];
            ushort_t hi, lo; bsplit(s, hi, lo);
            g_W0h[j*G4 + mp] = hi; g_W0l[j*G4 + mp] = lo;
        } else {
            int m = idx - 34*G4;
            int mp = ((m & 511) << 2) | (m >> 9);
            const float* wr = Wih0 + m*563;
            float s = bih0[m] + bhh0[m];
            #pragma unroll 4
            for (int d = 0; d < 512; d++) s += embed_b[d] * wr[d];
            g_bias0[mp] = s;
        }
    }
}

// ---------------- setup kernel 2: packs/copies ----------------
__global__ void k_setup_copy(const float* __restrict__ x,
                             const float* __restrict__ init,
                             const float* __restrict__ Wih0,
                             const float* __restrict__ Whh0,
                             const float* __restrict__ Wih1,
                             const float* __restrict__ Whh1,
                             const float* __restrict__ bih1,
                             const float* __restrict__ bhh1,
                             const float* __restrict__ niW1) {
    const int S1 = 574*G4;            // W0 rows 34..607
    const int S2 = 1024*G4;           // W1
    const int S3 = G4;                // bias1
    const int S4 = BATCH*96;          // initp
    const int S5 = 96*DDIM;           // niW1p
    const int S6 = BATCH*85;          // X0[0] cols 0..84 (x_0 | pred0)
    const int S7 = BATCH*22;          // X0 pad cols 597..607, both buffers
    const int TOT = S1+S2+S3+S4+S5+S6+S7;
    int i = blockIdx.x * blockDim.x + threadIdx.x;
    for (; i < TOT; i += gridDim.x * blockDim.x) {
        int r = i;
        if (r < S1) {
            int m = r & 2047; int k = 34 + (r >> 11);
            int mp = ((m & 511) << 2) | (m >> 9);
            float v;
            if (k < 85)       v = Wih0[m*563 + 512 + (k-34)];
            else if (k < 597) v = Whh0[m*512 + (k-85)];
            else              v = 0.f;
            ushort_t hi, lo; bsplit(v, hi, lo);
            g_W0h[k*G4 + mp] = hi; g_W0l[k*G4 + mp] = lo;
            continue;
        }
        r -= S1;
        if (r < S2) {
            int m = r & 2047; int k = r >> 11;
            int mp = ((m & 511) << 2) | (m >> 9);
            float v = (k < 512) ? Wih1[m*512 + k] : Whh1[m*512 + (k-512)];
            ushort_t hi, lo; bsplit(v, hi, lo);
            g_W1h[k*G4 + mp] = hi; g_W1l[k*G4 + mp] = lo;
            continue;
        }
        r -= S2;
        if (r < S3) {
            int mp = ((r & 511) << 2) | (r >> 9);
            g_bias1[mp] = bih1[r] + bhh1[r]; continue;
        }
        r -= S3;
        if (r < S4) { int b = r/96, j = r - b*96; g_initp[r] = (j < 85) ? init[b*85 + j] : 0.f; continue; }
        r -= S4;
        if (r < S5) { int k = r >> 9;  g_niW1p[r] = (k < 85) ? niW1[r] : 0.f; continue; }
        r -= S5;
        if (r < S6) {
            int b = r/85, j = r - b*85;
            float v = (j < 34) ? x[(b*FRAMES)*IN_DIM + j] : init[b*85 + (j-34)];
            ushort_t hi, lo; bsplit(v, hi, lo);
            g_X0h[0][b*K0 + j] = hi; g_X0l[0][b*K0 + j] = lo;
            continue;
        }
        r -= S6;
        {
            int b = r/22, jj = r - b*22;
            int buf = jj/11, col = 597 + (jj%11);
            g_X0h[buf][b*K0 + col] = 0; g_X0l[buf][b*K0 + col] = 0;
        }
    }
}

// ---------------- generic tiled GEMM (init MLP only; fp32 scalar) -----------
template<bool RELU>
__device__ __forceinline__ void gemm_nt(const float* __restrict__ A, int lda,
                                        const float* __restrict__ B, int ldb,
                                        float* __restrict__ C, int ldc,
                                        int M, int N, int K,
                                        const float* __restrict__ bias,
                                        float* sm) {
    float* As = sm;             // [16][68]
    float* Bs = sm + 16*68;     // [16][64]
    const int tid = threadIdx.x;
    const int nT = N >> 6;
    const int ntiles = (M >> 6) * nT;
    const int ar = tid >> 2, ac = (tid & 3) << 2;
    const int bk = tid >> 4, bn = (tid & 15) << 2;
    const int ty = tid >> 4, tx = tid & 15;
    for (int tile = blockIdx.x; tile < ntiles; tile += gridDim.x) {
        const int m0 = (tile / nT) << 6;
        const int n0 = (tile - (tile / nT) * nT) << 6;
        float4 acc0 = make_float4(0,0,0,0), acc1 = acc0, acc2 = acc0, acc3 = acc0;
        for (int k0 = 0; k0 < K; k0 += 16) {
            float4 va = __ldcg((const float4*)(A + (m0 + ar)*lda + k0 + ac));
            float4 vb = __ldg ((const float4*)(B + (k0 + bk)*ldb + n0 + bn));
            As[(ac+0)*68 + ar] = va.x;
            As[(ac+1)*68 + ar] = va.y;
            As[(ac+2)*68 + ar] = va.z;
            As[(ac+3)*68 + ar] = va.w;
            *(float4*)(Bs + bk*64 + bn) = vb;
            __syncthreads();
            #pragma unroll
            for (int kk = 0; kk < 16; kk++) {
                float4 a = *(const float4*)(As + kk*68 + (ty << 2));
                float4 b = *(const float4*)(Bs + kk*64 + (tx << 2));
                acc0.x += a.x*b.x; acc0.y += a.x*b.y; acc0.z += a.x*b.z; acc0.w += a.x*b.w;
                acc1.x += a.y*b.x; acc1.y += a.y*b.y; acc1.z += a.y*b.z; acc1.w += a.y*b.w;
                acc2.x += a.z*b.x; acc2.y += a.z*b.y; acc2.z += a.z*b.z; acc2.w += a.z*b.w;
                acc3.x += a.w*b.x; acc3.y += a.w*b.y; acc3.z += a.w*b.z; acc3.w += a.w*b.w;
            }
            __syncthreads();
        }
        float4 bb = __ldg((const float4*)(bias + n0 + (tx << 2)));
        float4 accs[4] = {acc0, acc1, acc2, acc3};
        #pragma unroll
        for (int i = 0; i < 4; i++) {
            float4 v = accs[i];
            v.x += bb.x; v.y += bb.y; v.z += bb.z; v.w += bb.w;
            if (RELU) { v.x = fmaxf(v.x, 0.f); v.y = fmaxf(v.y, 0.f);
                        v.z = fmaxf(v.z, 0.f); v.w = fmaxf(v.w, 0.f); }
            __stcg((float4*)(C + (m0 + (ty << 2) + i)*ldc + n0 + (tx << 2)), v);
        }
    }
}

// ---------------- fused MMA GEMM + LSTM-cell epilogue ----------------
// gates = (Ah+Al) @ (Wh+Wl) approx by 3 bf16 MMA terms, fp32 accumulate.
// 64x64 tile per CTA (blockIdx.x), 8 warps as 2(m) x 4(n), warp tile 32x16.
// smem per buffer (halves): Ah[64x24] @0, Al @1536, Wh[16x72] @3072, Wl @4224; buf stride 5376.
template<int LAYER>
__device__ __forceinline__ void gemm_cell_mma(
    const ushort_t* __restrict__ Ah, const ushort_t* __restrict__ Al, int K,
    const ushort_t* __restrict__ Wh, const ushort_t* __restrict__ Wl,
    const float* __restrict__ bias,
    float* __restrict__ cArr,
    ushort_t* __restrict__ X0nh, ushort_t* __restrict__ X0nl,
    ushort_t* __restrict__ X1ch, ushort_t* __restrict__ X1cl,
    ushort_t* __restrict__ X1nh, ushort_t* __restrict__ X1nl,
    float* __restrict__ out_mc, int t,
    ushort_t* sm)
{
    const int tid = threadIdx.x;
    const int l = tid & 31, w = tid >> 5;
    const int wm = w >> 2, wn = w & 3;
    const int m0 = (blockIdx.x >> 5) << 6;
    const int n0 = (blockIdx.x & 31) << 6;

    // staging indices
    const int sxr = tid >> 2, sxs = (tid & 3) << 2;   // X: 64 rows x 16 halves (uint2 per thread)
    const int swh = tid >> 7;                          // W: 0=hi, 1=lo
    const int swr = (tid >> 3) & 15, sws = (tid & 7) << 3;

    const unsigned int smb = (unsigned int)__cvta_generic_to_shared(sm);

    float D[2][2][4];
    #pragma unroll
    for (int a = 0; a < 2; a++)
        #pragma unroll
        for (int b = 0; b < 2; b++)
            #pragma unroll
            for (int k = 0; k < 4; k++) D[a][b][k] = 0.f;

    const int NC = K >> 4;

    // prologue: chunk 0 into buffer 0
    uint2 xh = __ldcg((const uint2*)(Ah + (m0+sxr)*K + sxs));
    uint2 xl = __ldcg((const uint2*)(Al + (m0+sxr)*K + sxs));
    uint4 wv = *(const uint4*)((swh ? Wl : Wh) + swr*G4 + n0 + sws);
    {
        ushort_t* buf = sm;
        *(uint2*)(buf + sxr*24 + sxs) = xh;
        *(uint2*)(buf + 1536 + sxr*24 + sxs) = xl;
        *(uint4*)(buf + 3072 + swh*1152 + swr*72 + sws) = wv;
    }
    __syncthreads();

    // precomputed lane addresses (byte offsets within a buffer)
    const unsigned int a_off = wm*1536 + (l & 15)*48 + (l >> 4)*16;
    const unsigned int b_off = 6144 + ((l & 7) + ((l >> 3) & 1)*8)*144
                             + (wn*16 + (l >> 4)*8)*2;

    int p = 0;
    for (int kc = 0; kc < NC; kc++) {
        const bool pre = (kc + 1 < NC);
        if (pre) {
            const int k0 = (kc + 1) << 4;
            xh = __ldcg((const uint2*)(Ah + (m0+sxr)*K + k0 + sxs));
            xl = __ldcg((const uint2*)(Al + (m0+sxr)*K + k0 + sxs));
            wv = *(const uint4*)((swh ? Wl : Wh) + (k0+swr)*G4 + n0 + sws);
        }
        const unsigned int bb = smb + p*10752u;
        unsigned int ah0[4], ah1[4], al0[4], al1[4], bh[4], bl[4];
        LDSM4 (ah0, bb + a_off);
        LDSM4 (ah1, bb + a_off + 768);
        LDSM4 (al0, bb + a_off + 3072);
        LDSM4 (al1, bb + a_off + 3072 + 768);
        LDSM4T(bh,  bb + b_off);
        LDSM4T(bl,  bb + b_off + 2304);
        // 12 MMAs: hi*hi, hi*lo, lo*hi
        MMA_BF16(D[0][0], ah0, bh[0], bh[1]); MMA_BF16(D[0][1], ah0, bh[2], bh[3]);
        MMA_BF16(D[1][0], ah1, bh[0], bh[1]); MMA_BF16(D[1][1], ah1, bh[2], bh[3]);
        MMA_BF16(D[0][0], ah0, bl[0], bl[1]); MMA_BF16(D[0][1], ah0, bl[2], bl[3]);
        MMA_BF16(D[1][0], ah1, bl[0], bl[1]); MMA_BF16(D[1][1], ah1, bl[2], bl[3]);
        MMA_BF16(D[0][0], al0, bh[0], bh[1]); MMA_BF16(D[0][1], al0, bh[2], bh[3]);
        MMA_BF16(D[1][0], al1, bh[0], bh[1]); MMA_BF16(D[1][1], al1, bh[2], bh[3]);
        if (pre) {
            ushort_t* buf = sm + (p ^ 1)*5376;
            *(uint2*)(buf + sxr*24 + sxs) = xh;
            *(uint2*)(buf + 1536 + sxr*24 + sxs) = xl;
            *(uint4*)(buf + 3072 + swh*1152 + swr*72 + sws) = wv;
        }
        __syncthreads();
        p ^= 1;
    }

    // ---- epilogue: LSTM cell on (i,f,g,o) quads via pair shuffle ----
    const int tig = l & 3, r = l >> 2;
    const int nw = n0 + wn*16;
    const int mw = m0 + wm*32;
    #pragma unroll
    for (int mf = 0; mf < 2; mf++) {
        float oth[4];
        #pragma unroll
        for (int k = 0; k < 4; k++) {
            float send = (tig & 1) ? D[mf][0][k] : D[mf][1][k];
            oth[k] = __shfl_xor_sync(0xffffffffu, send, 1);
        }
        const int nf = (tig & 1);
        const int dd = (nw >> 2) + nf*2 + (tig >> 1);
        const float4 bb4 = __ldg((const float4*)(bias + 4*dd));
        float iv[2], fv[2], gv[2], ov[2];
        if (!nf) {   // even lane: own frag0 = (i,f); partner's = (g,o)
            iv[0] = D[mf][0][0]; fv[0] = D[mf][0][1]; gv[0] = oth[0]; ov[0] = oth[1];
            iv[1] = D[mf][0][2]; fv[1] = D[mf][0][3]; gv[1] = oth[2]; ov[1] = oth[3];
        } else {     // odd lane: own frag1 = (g,o); partner's = (i,f)
            iv[0] = oth[0]; fv[0] = oth[1]; gv[0] = D[mf][1][0]; ov[0] = D[mf][1][1];
            iv[1] = oth[2]; fv[1] = oth[3]; gv[1] = D[mf][1][2]; ov[1] = D[mf][1][3];
        }
        #pragma unroll
        for (int rr = 0; rr < 2; rr++) {
            const int b = mw + mf*16 + r + rr*8;
            float ig = sigf (iv[rr] + bb4.x);
            float fg = sigf (fv[rr] + bb4.y);
            float gg = tanhg(gv[rr] + bb4.z);
            float og = sigf (ov[rr] + bb4.w);
            float c  = fg * cArr[b*DDIM + dd] + ig * gg;   // CTA-private
            cArr[b*DDIM + dd] = c;
            float h = og * tanhg(c);
            ushort_t hh, hl; bsplit(h, hh, hl);
            if (LAYER == 0) {
                st_cg_u16(&X1ch[b*K1 + dd], hh);
                st_cg_u16(&X1cl[b*K1 + dd], hl);
                st_cg_u16(&X0nh[b*K0 + 85 + dd], hh);
                st_cg_u16(&X0nl[b*K0 + 85 + dd], hl);
            } else {
                st_cg_u16(&X1nh[b*K1 + 512 + dd], hh);
                st_cg_u16(&X1nl[b*K1 + 512 + dd], hl);
                out_mc[((long)b*FRAMES + t)*563 + dd] = h;
            }
        }
    }
}

// ---------------- persistent scan kernel ----------------
__global__ void __launch_bounds__(THREADS, 1)
k_persist(const float* __restrict__ x,
          const float* __restrict__ niW2, const float* __restrict__ niW3,
          const float* __restrict__ nb1,  const float* __restrict__ nb2,
          const float* __restrict__ nb3,
          const float* __restrict__ decW, const float* __restrict__ decb,
          float* __restrict__ out_pred, float* __restrict__ out_mc) {
    __shared__ __align__(16) ushort_t smem[2*5376];   // 21.5 KB; reused by all phases
    float* smf = (float*)smem;
    const int gtid = blockIdx.x * THREADS + threadIdx.x;

    // ---- init network (fp32 scalar path; runs once) ----
    gemm_nt<true >(g_initp, 96,   g_niW1p, DDIM, g_z1, DDIM, BATCH, DDIM, 96,   nb1, smf);
    grid_sync();
    gemm_nt<true >(g_z1,   DDIM,  niW2,    1024, g_z2, 1024, BATCH, 1024, DDIM, nb2, smf);
    grid_sync();
    gemm_nt<false>(g_z2,   1024,  niW3,    2048, g_z3, 2048, BATCH, 2048, 1024, nb3, smf);
    grid_sync();
    for (int idx = gtid; idx < BATCH*DDIM; idx += NT) {
        int b = idx >> 9, d = idx & 511;
        const float* zr = g_z3 + b*2048;
        ushort_t hi, lo;
        bsplit(__ldcg(zr + d), hi, lo);                       // h0 init
        st_cg_u16(&g_X0h[0][b*K0 + 85 + d], hi); st_cg_u16(&g_X0l[0][b*K0 + 85 + d], lo);
        bsplit(__ldcg(zr + 512 + d), hi, lo);                 // h1 init
        st_cg_u16(&g_X1h[0][b*K1 + 512 + d], hi); st_cg_u16(&g_X1l[0][b*K1 + 512 + d], lo);
        __stcg(&g_c0[idx], __ldcg(zr + 1024 + d));
        __stcg(&g_c1[idx], __ldcg(zr + 1536 + d));
    }
    grid_sync();

    // ---- scan: 3 grid syncs per step ----
    for (int t = 0; t < FRAMES; t++) {
        const int cur = t & 1, nxt = cur ^ 1;

        // phase A: gates0 MMA GEMM + cell0 epilogue
        gemm_cell_mma<0>(g_X0h[cur], g_X0l[cur], K0, g_W0h, g_W0l, g_bias0, g_c0,
                         g_X0h[nxt], g_X0l[nxt], g_X1h[cur], g_X1l[cur],
                         nullptr, nullptr, nullptr, t, smem);
        grid_sync();

        // phase B: gates1 MMA GEMM + cell1 epilogue
        gemm_cell_mma<1>(g_X1h[cur], g_X1l[cur], K1, g_W1h, g_W1l, g_bias1, g_c1,
                         nullptr, nullptr, nullptr, nullptr,
                         g_X1h[nxt], g_X1l[nxt], out_mc, t, smem);
        grid_sync();

        // phase C: decoder + next-step x copy (block -> 2 batch rows)
        {
            float* h1s = smf;                    // 1024 floats
            const int b0 = blockIdx.x << 1;
            for (int i = threadIdx.x; i < 1024; i += THREADS) {
                int bb = i >> 9, d = i & 511;
                long off = (long)(b0 + bb)*K1 + 512 + d;
                h1s[i] = bjoin(ld_cg_u16(&g_X1h[nxt][off]), ld_cg_u16(&g_X1l[nxt][off]));
            }
            __syncthreads();
            int bb = threadIdx.x >> 7, jj = threadIdx.x & 127;
            if (jj < NJ3) {
                int b = b0 + bb;
                float s = __ldg(&decb[jj]);
                const float* hr = h1s + (bb << 9);
                #pragma unroll 8
                for (int d = 0; d < 512; d++) s += hr[d] * __ldg(&decW[d*NJ3 + jj]);
                long bt = (long)b*FRAMES + t;
                out_pred[bt*NJ3 + jj] = s;
                out_mc[bt*563 + 512 + jj] = s;
                ushort_t hi, lo; bsplit(s, hi, lo);
                st_cg_u16(&g_X0h[nxt][b*K0 + 34 + jj], hi);
                st_cg_u16(&g_X0l[nxt][b*K0 + 34 + jj], lo);
            }
            if (t + 1 < FRAMES) {
                for (int i = threadIdx.x; i < 2*IN_DIM; i += THREADS) {
                    int bb2 = i / IN_DIM, j = i - bb2*IN_DIM;
                    int b = b0 + bb2;
                    float v = __ldg(&x[((long)b*FRAMES + t + 1)*IN_DIM + j]);
                    ushort_t hi, lo; bsplit(v, hi, lo);
                    st_cg_u16(&g_X0h[nxt][b*K0 + j], hi);
                    st_cg_u16(&g_X0l[nxt][b*K0 + j], lo);
                }
            }
        }
        grid_sync();
    }
}

// ---------------- entry ----------------
extern "C" void kernel_launch(void* const* d_in, const int* in_sizes, int n_in,
                              void* d_out, int out_size) {
    const float* x       = (const float*)d_in[0];
    const float* init_   = (const float*)d_in[1];
    const float* embed_W = (const float*)d_in[2];
    const float* embed_b = (const float*)d_in[3];
    const float* ni_W1   = (const float*)d_in[4];
    const float* ni_b1   = (const float*)d_in[5];
    const float* ni_W2   = (const float*)d_in[6];
    const float* ni_b2   = (const float*)d_in[7];
    const float* ni_W3   = (const float*)d_in[8];
    const float* ni_b3   = (const float*)d_in[9];
    const float* Wih0    = (const float*)d_in[10];
    const float* Whh0    = (const float*)d_in[11];
    const float* bih0    = (const float*)d_in[12];
    const float* bhh0    = (const float*)d_in[13];
    const float* Wih1    = (const float*)d_in[14];
    const float* Whh1    = (const float*)d_in[15];
    const float* bih1    = (const float*)d_in[16];
    const float* bhh1    = (const float*)d_in[17];
    const float* dec_W   = (const float*)d_in[18];
    const float* dec_b   = (const float*)d_in[19];

    float* out_pred = (float*)d_out;                              // (256,256,17,3)
    float* out_mc   = out_pred + (long)BATCH*FRAMES*NJ3;          // (256,256,563)

    k_setup_heavy<<<280, 256>>>(embed_W, embed_b, Wih0, bih0, bhh0);
    k_setup_copy <<<2048, 256>>>(x, init_, Wih0, Whh0, Wih1, Whh1, bih1, bhh1, ni_W1);
    k_persist    <<<GRID, THREADS>>>(x, ni_W2, ni_W3, ni_b1, ni_b2, ni_b3,
                                     dec_W, dec_b, out_pred, out_mc);
}

// round 10
// speedup vs baseline: 2.2063x; 1.5215x over previous
#include <cuda_runtime.h>
#include <cuda_bf16.h>

// ---------------- problem constants ----------------
#define BATCH 256
#define FRAMES 256
#define IN_DIM 34
#define NJ3 51
#define DDIM 512
#define G4 2048            // 4*D
#define K0X 1120           // 34 x | 51 predc | 512 h0 | 512 h1 | 11 pad
#define K1 1024            // 512 h0n | 512 h1prev
#define GRID 128
#define THREADS 256
#define NT (GRID*THREADS)
#define STG_HALVES 5376    // per-stage smem halves: Ah 1536 | Al 1536 | Wh 1152 | Wl 1152
#define STG_BYTES 10752

typedef unsigned short ushort_t;

// ---------------- PTX helpers ----------------
#define LDSM4(R, addr) asm volatile( \
    "ldmatrix.sync.aligned.m8n8.x4.shared.b16 {%0,%1,%2,%3},[%4];" \
    : "=r"((R)[0]),"=r"((R)[1]),"=r"((R)[2]),"=r"((R)[3]) : "r"(addr))
#define LDSM4T(R, addr) asm volatile( \
    "ldmatrix.sync.aligned.m8n8.x4.trans.shared.b16 {%0,%1,%2,%3},[%4];" \
    : "=r"((R)[0]),"=r"((R)[1]),"=r"((R)[2]),"=r"((R)[3]) : "r"(addr))
#define MMA_BF16(D, A, b0, b1) asm volatile( \
    "mma.sync.aligned.m16n8k16.row.col.f32.bf16.bf16.f32 " \
    "{%0,%1,%2,%3},{%4,%5,%6,%7},{%8,%9},{%0,%1,%2,%3};" \
    : "+f"((D)[0]),"+f"((D)[1]),"+f"((D)[2]),"+f"((D)[3]) \
    : "r"((A)[0]),"r"((A)[1]),"r"((A)[2]),"r"((A)[3]),"r"(b0),"r"(b1))
#define CP_ASYNC16(dst, src) asm volatile( \
    "cp.async.cg.shared.global [%0], [%1], 16;" :: "r"(dst), "l"(src))
#define CP_COMMIT() asm volatile("cp.async.commit_group;")
#define CP_WAIT2()  asm volatile("cp.async.wait_group 2;")

__device__ __forceinline__ void st_cg_u16(ushort_t* p, ushort_t v) {
    asm volatile("st.global.cg.u16 [%0], %1;" :: "l"(p), "h"(v));
}
__device__ __forceinline__ ushort_t ld_cg_u16(const ushort_t* p) {
    ushort_t v; asm volatile("ld.global.cg.u16 %0, [%1];" : "=h"(v) : "l"(p)); return v;
}
__device__ __forceinline__ void bsplit(float v, ushort_t& hi, ushort_t& lo) {
    __nv_bfloat16 h = __float2bfloat16(v);
    __nv_bfloat16 l2 = __float2bfloat16(v - __bfloat162float(h));
    hi = *(ushort_t*)&h; lo = *(ushort_t*)&l2;
}

// ---------------- device scratch ----------------
// Gate-interleaved weights, split bf16: column m' = 4*d + gate (0=i,1=f,2=g,3=o)
__device__ ushort_t g_W0h[K0X*G4];
__device__ ushort_t g_W0l[K0X*G4];
__device__ ushort_t g_W1h[K1*G4];
__device__ ushort_t g_W1l[K1*G4];
__device__ float g_bias0[G4];
__device__ float g_bias1[G4];
__device__ float g_initp[BATCH*96];
__device__ float g_niW1p[96*DDIM];
__device__ float g_z1[BATCH*DDIM];
__device__ float g_z2[BATCH*1024];
__device__ float g_z3[BATCH*2048];
__device__ float g_decWp[512*64];     // decW padded 51->64 cols
__device__ float g_decbp[64];
// Ping-pong activations, split bf16
__device__ ushort_t g_X0h[2][BATCH*K0X];
__device__ ushort_t g_X0l[2][BATCH*K0X];
__device__ ushort_t g_X1h[2][BATCH*K1];
__device__ ushort_t g_X1l[2][BATCH*K1];
__device__ float g_c0[BATCH*DDIM];
__device__ float g_c1[BATCH*DDIM];

// barrier state
__device__ unsigned int g_arrive;
__device__ volatile unsigned int g_release;

__device__ __forceinline__ void grid_sync() {
    __threadfence();
    __syncthreads();
    if (threadIdx.x == 0) {
        unsigned int gen = g_release;
        unsigned int prev = atomicAdd(&g_arrive, 1u);
        if (prev == gridDim.x - 1u) {
            g_arrive = 0u;
            __threadfence();
            g_release = gen + 1u;
        } else {
            while (g_release == gen) { __nanosleep(32); }
        }
        __threadfence();
    }
    __syncthreads();
}

__device__ __forceinline__ float sigf(float v)  { return 1.0f / (1.0f + __expf(-v)); }
__device__ __forceinline__ float tanhg(float v) { float e = __expf(2.0f*v); return 1.0f - 2.0f/(e + 1.0f); }

// ---------------- setup kernel 1: folded x-weight, decoder fold, bias0 ----------------
__global__ void k_setup_heavy(const float* __restrict__ embed_W,
                              const float* __restrict__ embed_b,
                              const float* __restrict__ Wih0,
                              const float* __restrict__ bih0,
                              const float* __restrict__ bhh0,
                              const float* __restrict__ decW,
                              const float* __restrict__ decb) {
    int idx = blockIdx.x * blockDim.x + threadIdx.x;
    const int TOT = 35*G4 + 512*G4;
    for (; idx < TOT; idx += gridDim.x * blockDim.x) {
        if (idx < 34*G4) {                               // rows 0..33: embed fold
            int m = idx & 2047, j = idx >> 11;
            int mp = ((m & 511) << 2) | (m >> 9);
            const float* wr = Wih0 + m*563;
            const float* er = embed_W + j*512;
            float s = 0.f;
            #pragma unroll 4
            for (int d = 0; d < 512; d++) s += er[d] * wr[d];
            ushort_t hi, lo; bsplit(s, hi, lo);
            g_W0h[j*G4 + mp] = hi; g_W0l[j*G4 + mp] = lo;
        } else if (idx < 35*G4) {                        // bias0 = bih0+bhh0+embed_b@Wx^T+decb@Wp
            int m = idx - 34*G4;
            int mp = ((m & 511) << 2) | (m >> 9);
            const float* wr = Wih0 + m*563;
            float s = bih0[m] + bhh0[m];
            #pragma unroll 4
            for (int d = 0; d < 512; d++) s += embed_b[d] * wr[d];
            for (int j = 0; j < NJ3; j++) s += decb[j] * wr[512 + j];
            g_bias0[mp] = s;
        } else {                                          // rows 597..1108: decW @ Wp fold
            int r = idx - 35*G4;
            int m = r & 2047, d = r >> 11;
            int mp = ((m & 511) << 2) | (m >> 9);
            const float* wr = Wih0 + m*563 + 512;
            const float* dr = decW + d*NJ3;
            float s = 0.f;
            for (int j = 0; j < NJ3; j++) s += dr[j] * wr[j];
            ushort_t hi, lo; bsplit(s, hi, lo);
            g_W0h[(597+d)*G4 + mp] = hi; g_W0l[(597+d)*G4 + mp] = lo;
        }
    }
}

// ---------------- setup kernel 2: packs/copies ----------------
__global__ void k_setup_copy(const float* __restrict__ x,
                             const float* __restrict__ init,
                             const float* __restrict__ Wih0,
                             const float* __restrict__ Whh0,
                             const float* __restrict__ Wih1,
                             const float* __restrict__ Whh1,
                             const float* __restrict__ bih1,
                             const float* __restrict__ bhh1,
                             const float* __restrict__ niW1,
                             const float* __restrict__ decW,
                             const float* __restrict__ decb) {
    const int S1 = 563*G4;            // W0 rows 34..596 (Wp | Whh0)
    const int S1b = 11*G4;            // W0 pad rows 1109..1119
    const int S2 = 1024*G4;           // W1
    const int S3 = G4;                // bias1
    const int S4 = BATCH*96;          // initp
    const int S5 = 96*DDIM;           // niW1p
    const int S6 = BATCH*85;          // X0[0] cols 0..84 (x_0 | pred0-decb)
    const int S7 = BATCH*585;         // X0 zero regions (buf0: h1+pad = 523; buf1: predc+pad = 62)
    const int S8 = 512*64 + 64;       // decWp + decbp
    const int TOT = S1+S1b+S2+S3+S4+S5+S6+S7+S8;
    int i = blockIdx.x * blockDim.x + threadIdx.x;
    for (; i < TOT; i += gridDim.x * blockDim.x) {
        int r = i;
        if (r < S1) {
            int m = r & 2047; int k = 34 + (r >> 11);
            int mp = ((m & 511) << 2) | (m >> 9);
            float v = (k < 85) ? Wih0[m*563 + 512 + (k-34)] : Whh0[m*512 + (k-85)];
            ushort_t hi, lo; bsplit(v, hi, lo);
            g_W0h[k*G4 + mp] = hi; g_W0l[k*G4 + mp] = lo;
            continue;
        }
        r -= S1;
        if (r < S1b) {
            int m = r & 2047; int k = 1109 + (r >> 11);
            int mp = ((m & 511) << 2) | (m >> 9);
            g_W0h[k*G4 + mp] = 0; g_W0l[k*G4 + mp] = 0;
            continue;
        }
        r -= S1b;
        if (r < S2) {
            int m = r & 2047; int k = r >> 11;
            int mp = ((m & 511) << 2) | (m >> 9);
            float v = (k < 512) ? Wih1[m*512 + k] : Whh1[m*512 + (k-512)];
            ushort_t hi, lo; bsplit(v, hi, lo);
            g_W1h[k*G4 + mp] = hi; g_W1l[k*G4 + mp] = lo;
            continue;
        }
        r -= S2;
        if (r < S3) {
            int mp = ((r & 511) << 2) | (r >> 9);
            g_bias1[mp] = bih1[r] + bhh1[r]; continue;
        }
        r -= S3;
        if (r < S4) { int b = r/96, j = r - b*96; g_initp[r] = (j < 85) ? init[b*85 + j] : 0.f; continue; }
        r -= S4;
        if (r < S5) { int k = r >> 9;  g_niW1p[r] = (k < 85) ? niW1[r] : 0.f; continue; }
        r -= S5;
        if (r < S6) {
            int b = r/85, j = r - b*85;
            float v = (j < 34) ? x[(b*FRAMES)*IN_DIM + j]
                               : init[b*85 + (j-34)] - decb[j-34];   // predc_0 = pred0 - decb
            ushort_t hi, lo; bsplit(v, hi, lo);
            g_X0h[0][b*K0X + j] = hi; g_X0l[0][b*K0X + j] = lo;
            continue;
        }
        r -= S6;
        if (r < S7) {
            int b = r/585, z = r - b*585;
            int buf, col;
            if (z < 523) { buf = 0; col = (z < 512) ? (597 + z) : (1109 + z - 512); }
            else { int zz = z - 523; buf = 1; col = (zz < NJ3) ? (34 + zz) : (1109 + zz - NJ3); }
            g_X0h[buf][b*K0X + col] = 0; g_X0l[buf][b*K0X + col] = 0;
            continue;
        }
        r -= S7;
        if (r < 512*64) { int k = r >> 6, j = r & 63; g_decWp[r] = (j < NJ3) ? decW[k*NJ3 + j] : 0.f; }
        else { int j = r - 512*64; g_decbp[j] = (j < NJ3) ? decb[j] : 0.f; }
    }
}

// ---------------- generic tiled GEMM (init MLP only; fp32 scalar) -----------
template<bool RELU>
__device__ __forceinline__ void gemm_nt(const float* __restrict__ A, int lda,
                                        const float* __restrict__ B, int ldb,
                                        float* __restrict__ C, int ldc,
                                        int M, int N, int K,
                                        const float* __restrict__ bias,
                                        float* sm) {
    float* As = sm;             // [16][68]
    float* Bs = sm + 16*68;     // [16][64]
    const int tid = threadIdx.x;
    const int nT = N >> 6;
    const int ntiles = (M >> 6) * nT;
    const int ar = tid >> 2, ac = (tid & 3) << 2;
    const int bk = tid >> 4, bn = (tid & 15) << 2;
    const int ty = tid >> 4, tx = tid & 15;
    for (int tile = blockIdx.x; tile < ntiles; tile += gridDim.x) {
        const int m0 = (tile / nT) << 6;
        const int n0 = (tile - (tile / nT) * nT) << 6;
        float4 acc0 = make_float4(0,0,0,0), acc1 = acc0, acc2 = acc0, acc3 = acc0;
        for (int k0 = 0; k0 < K; k0 += 16) {
            float4 va = __ldcg((const float4*)(A + (m0 + ar)*lda + k0 + ac));
            float4 vb = __ldg ((const float4*)(B + (k0 + bk)*ldb + n0 + bn));
            As[(ac+0)*68 + ar] = va.x;
            As[(ac+1)*68 + ar] = va.y;
            As[(ac+2)*68 + ar] = va.z;
            As[(ac+3)*68 + ar] = va.w;
            *(float4*)(Bs + bk*64 + bn) = vb;
            __syncthreads();
            #pragma unroll
            for (int kk = 0; kk < 16; kk++) {
                float4 a = *(const float4*)(As + kk*68 + (ty << 2));
                float4 b = *(const float4*)(Bs + kk*64 + (tx << 2));
                acc0.x += a.x*b.x; acc0.y += a.x*b.y; acc0.z += a.x*b.z; acc0.w += a.x*b.w;
                acc1.x += a.y*b.x; acc1.y += a.y*b.y; acc1.z += a.y*b.z; acc1.w += a.y*b.w;
                acc2.x += a.z*b.x; acc2.y += a.z*b.y; acc2.z += a.z*b.z; acc2.w += a.z*b.w;
                acc3.x += a.w*b.x; acc3.y += a.w*b.y; acc3.z += a.w*b.z; acc3.w += a.w*b.w;
            }
            __syncthreads();
        }
        float4 bb = __ldg((const float4*)(bias + n0 + (tx << 2)));
        float4 accs[4] = {acc0, acc1, acc2, acc3};
        #pragma unroll
        for (int i = 0; i < 4; i++) {
            float4 v = accs[i];
            v.x += bb.x; v.y += bb.y; v.z += bb.z; v.w += bb.w;
            if (RELU) { v.x = fmaxf(v.x, 0.f); v.y = fmaxf(v.y, 0.f);
                        v.z = fmaxf(v.z, 0.f); v.w = fmaxf(v.w, 0.f); }
            __stcg((float4*)(C + (m0 + (ty << 2) + i)*ldc + n0 + (tx << 2)), v);
        }
    }
}

// ---------------- fused MMA GEMM + LSTM-cell epilogue (4-stage cp.async) --------------
// gates = (Ah+Al) @ (Wh+Wl) approx by 3 bf16 MMA terms, fp32 accumulate.
// 64x64 tile per CTA (blockIdx.x), 8 warps as 2(m) x 4(n), warp tile 32x16.
// Stage layout (halves): Ah[64x24] @0, Al @1536, Wh[16x72] @3072, Wl @4224.
template<int LAYER>
__device__ __forceinline__ void gemm_cell_mma(
    const ushort_t* __restrict__ Ah, const ushort_t* __restrict__ Al, int K,
    const ushort_t* __restrict__ Wh, const ushort_t* __restrict__ Wl,
    const float* __restrict__ bias,
    float* __restrict__ cArr,
    ushort_t* __restrict__ X0nh, ushort_t* __restrict__ X0nl,
    ushort_t* __restrict__ X1ah, ushort_t* __restrict__ X1al,   // layer0: X1cur; layer1: X1next
    float* __restrict__ out_mc, int t,
    ushort_t* sm)
{
    const int tid = threadIdx.x;
    const int l = tid & 31, w = tid >> 5;
    const int wm = w >> 2, wn = w & 3;
    const int m0 = (blockIdx.x >> 5) << 6;
    const int n0 = (blockIdx.x & 31) << 6;

    // cp.async staging mapping (2 x 16B per thread)
    const int hl  = tid >> 7;
    const int a_r = (tid >> 1) & 63, a_c = (tid & 1) << 3;
    const int w_r = (tid >> 3) & 15, w_c = (tid & 7) << 3;
    const unsigned int a_dst = (hl*1536 + a_r*24 + a_c) * 2;
    const unsigned int w_dst = (3072 + hl*1152 + w_r*72 + w_c) * 2;
    const ushort_t* a_src = (hl ? Al : Ah) + (m0 + a_r)*K + a_c;
    const ushort_t* w_src = (hl ? Wl : Wh) + (long)w_r*G4 + n0 + w_c;

    const unsigned int smb = (unsigned int)__cvta_generic_to_shared(sm);

    float D[2][2][4];
    #pragma unroll
    for (int a = 0; a < 2; a++)
        #pragma unroll
        for (int b = 0; b < 2; b++)
            #pragma unroll
            for (int k = 0; k < 4; k++) D[a][b][k] = 0.f;

    const int NC = K >> 4;

    // prologue: issue chunks 0..2
    #pragma unroll
    for (int s = 0; s < 3; s++) {
        unsigned int base = smb + s*STG_BYTES;
        CP_ASYNC16(base + a_dst, a_src + (s << 4));
        CP_ASYNC16(base + w_dst, w_src + ((long)(s << 4))*G4);
        CP_COMMIT();
    }

    // lane addresses for LDSM (byte offsets within a stage)
    const unsigned int a_off = wm*1536 + (l & 15)*48 + (l >> 4)*16;
    const unsigned int b_off = 6144 + ((l & 7) + ((l >> 3) & 1)*8)*144
                             + (wn*16 + (l >> 4)*8)*2;

    for (int kc = 0; kc < NC; kc++) {
        CP_WAIT2();
        __syncthreads();
        if (kc + 3 < NC) {
            unsigned int base = smb + ((kc + 3) & 3)*STG_BYTES;
            CP_ASYNC16(base + a_dst, a_src + ((kc + 3) << 4));
            CP_ASYNC16(base + w_dst, w_src + ((long)((kc + 3) << 4))*G4);
        }
        CP_COMMIT();

        const unsigned int bb = smb + (kc & 3)*STG_BYTES;
        unsigned int ah0[4], ah1[4], al0[4], al1[4], bh[4], bl[4];
        LDSM4 (ah0, bb + a_off);
        LDSM4 (ah1, bb + a_off + 768);
        LDSM4 (al0, bb + a_off + 3072);
        LDSM4 (al1, bb + a_off + 3072 + 768);
        LDSM4T(bh,  bb + b_off);
        LDSM4T(bl,  bb + b_off + 2304);
        // 12 MMAs: hi*hi, hi*lo, lo*hi
        MMA_BF16(D[0][0], ah0, bh[0], bh[1]); MMA_BF16(D[0][1], ah0, bh[2], bh[3]);
        MMA_BF16(D[1][0], ah1, bh[0], bh[1]); MMA_BF16(D[1][1], ah1, bh[2], bh[3]);
        MMA_BF16(D[0][0], ah0, bl[0], bl[1]); MMA_BF16(D[0][1], ah0, bl[2], bl[3]);
        MMA_BF16(D[1][0], ah1, bl[0], bl[1]); MMA_BF16(D[1][1], ah1, bl[2], bl[3]);
        MMA_BF16(D[0][0], al0, bh[0], bh[1]); MMA_BF16(D[0][1], al0, bh[2], bh[3]);
        MMA_BF16(D[1][0], al1, bh[0], bh[1]); MMA_BF16(D[1][1], al1, bh[2], bh[3]);
    }

    // ---- epilogue: LSTM cell on (i,f,g,o) quads via pair shuffle ----
    const int tig = l & 3, r = l >> 2;
    const int nw = n0 + wn*16;
    const int mw = m0 + wm*32;
    #pragma unroll
    for (int mf = 0; mf < 2; mf++) {
        float oth[4];
        #pragma unroll
        for (int k = 0; k < 4; k++) {
            float send = (tig & 1) ? D[mf][0][k] : D[mf][1][k];
            oth[k] = __shfl_xor_sync(0xffffffffu, send, 1);
        }
        const int nf = (tig & 1);
        const int dd = (nw >> 2) + nf*2 + (tig >> 1);
        const float4 bb4 = __ldg((const float4*)(bias + 4*dd));
        float iv[2], fv[2], gv[2], ov[2];
        if (!nf) {
            iv[0] = D[mf][0][0]; fv[0] = D[mf][0][1]; gv[0] = oth[0]; ov[0] = oth[1];
            iv[1] = D[mf][0][2]; fv[1] = D[mf][0][3]; gv[1] = oth[2]; ov[1] = oth[3];
        } else {
            iv[0] = oth[0]; fv[0] = oth[1]; gv[0] = D[mf][1][0]; ov[0] = D[mf][1][1];
            iv[1] = oth[2]; fv[1] = oth[3]; gv[1] = D[mf][1][2]; ov[1] = D[mf][1][3];
        }
        #pragma unroll
        for (int rr = 0; rr < 2; rr++) {
            const int b = mw + mf*16 + r + rr*8;
            float ig = sigf (iv[rr] + bb4.x);
            float fg = sigf (fv[rr] + bb4.y);
            float gg = tanhg(gv[rr] + bb4.z);
            float og = sigf (ov[rr] + bb4.w);
            float c  = fg * cArr[b*DDIM + dd] + ig * gg;   // CTA-private
            cArr[b*DDIM + dd] = c;
            float h = og * tanhg(c);
            ushort_t hh, hl2; bsplit(h, hh, hl2);
            if (LAYER == 0) {
                st_cg_u16(&X1ah[b*K1 + dd], hh);           // gates1 input (this step)
                st_cg_u16(&X1al[b*K1 + dd], hl2);
                st_cg_u16(&X0nh[b*K0X + 85 + dd], hh);     // recurrent h0 (next step)
                st_cg_u16(&X0nl[b*K0X + 85 + dd], hl2);
            } else {
                st_cg_u16(&X1ah[b*K1 + 512 + dd], hh);     // recurrent h1 (next step)
                st_cg_u16(&X1al[b*K1 + 512 + dd], hl2);
                st_cg_u16(&X0nh[b*K0X + 597 + dd], hh);    // h1 -> folded decoder input
                st_cg_u16(&X0nl[b*K0X + 597 + dd], hl2);
                out_mc[((long)b*FRAMES + t)*563 + dd] = h; // motion_context h part (fp32)
            }
        }
    }
}

// ---------------- persistent scan kernel ----------------
__global__ void __launch_bounds__(THREADS, 1)
k_persist(const float* __restrict__ x,
          const float* __restrict__ niW2, const float* __restrict__ niW3,
          const float* __restrict__ nb1,  const float* __restrict__ nb2,
          const float* __restrict__ nb3,
          float* __restrict__ out_mc) {
    __shared__ __align__(16) ushort_t smem[4*STG_HALVES];   // 43 KB
    float* smf = (float*)smem;
    const int gtid = blockIdx.x * THREADS + threadIdx.x;

    // ---- init network (fp32 scalar path; runs once) ----
    gemm_nt<true >(g_initp, 96,   g_niW1p, DDIM, g_z1, DDIM, BATCH, DDIM, 96,   nb1, smf);
    grid_sync();
    gemm_nt<true >(g_z1,   DDIM,  niW2,    1024, g_z2, 1024, BATCH, 1024, DDIM, nb2, smf);
    grid_sync();
    gemm_nt<false>(g_z2,   1024,  niW3,    2048, g_z3, 2048, BATCH, 2048, 1024, nb3, smf);
    grid_sync();
    for (int idx = gtid; idx < BATCH*DDIM; idx += NT) {
        int b = idx >> 9, d = idx & 511;
        const float* zr = g_z3 + b*2048;
        ushort_t hi, lo;
        bsplit(__ldcg(zr + d), hi, lo);                       // h0 init
        st_cg_u16(&g_X0h[0][b*K0X + 85 + d], hi); st_cg_u16(&g_X0l[0][b*K0X + 85 + d], lo);
        bsplit(__ldcg(zr + 512 + d), hi, lo);                 // h1 init
        st_cg_u16(&g_X1h[0][b*K1 + 512 + d], hi); st_cg_u16(&g_X1l[0][b*K1 + 512 + d], lo);
        __stcg(&g_c0[idx], __ldcg(zr + 1024 + d));
        __stcg(&g_c1[idx], __ldcg(zr + 1536 + d));
    }
    grid_sync();

    // ---- scan: 2 grid syncs per step ----
    for (int t = 0; t < FRAMES; t++) {
        const int cur = t & 1, nxt = cur ^ 1;

        // phase A: gates0 MMA GEMM (K=1120, decoder folded) + cell0 epilogue
        gemm_cell_mma<0>(g_X0h[cur], g_X0l[cur], K0X, g_W0h, g_W0l, g_bias0, g_c0,
                         g_X0h[nxt], g_X0l[nxt], g_X1h[cur], g_X1l[cur],
                         nullptr, t, smem);
        grid_sync();

        // phase B: gates1 MMA GEMM + cell1 epilogue
        gemm_cell_mma<1>(g_X1h[cur], g_X1l[cur], K1, g_W1h, g_W1l, g_bias1, g_c1,
                         g_X0h[nxt], g_X0l[nxt], g_X1h[nxt], g_X1l[nxt],
                         out_mc, t, smem);

        // x_{t+1} copy + one-time predc clear (n-tile-0 CTAs; 64 rows each)
        if ((blockIdx.x & 31) == 0) {
            const int mbase = (blockIdx.x >> 5) << 6;
            if (t + 1 < FRAMES) {
                for (int i = threadIdx.x; i < 64*IN_DIM; i += THREADS) {
                    int rr = i / IN_DIM, j = i - rr*IN_DIM;
                    int b = mbase + rr;
                    float v = __ldg(&x[((long)b*FRAMES + t + 1)*IN_DIM + j]);
                    ushort_t hi, lo; bsplit(v, hi, lo);
                    st_cg_u16(&g_X0h[nxt][b*K0X + j], hi);
                    st_cg_u16(&g_X0l[nxt][b*K0X + j], lo);
                }
            }
            if (t == 0) {   // buffer 0's predc (pred0-decb) becomes 0 for t>=2
                for (int i = threadIdx.x; i < 64*NJ3; i += THREADS) {
                    int rr = i / NJ3, j = i - rr*NJ3;
                    int b = mbase + rr;
                    st_cg_u16(&g_X0h[0][b*K0X + 34 + j], 0);
                    st_cg_u16(&g_X0l[0][b*K0X + 34 + j], 0);
                }
            }
        }
        grid_sync();
    }
}

// ---------------- post-scan decoder: preds = H1_all @ decW + decb ----------------
__global__ void __launch_bounds__(256)
k_decode(const float* __restrict__ mc_h,   // out_mc (h part, cols 0..511, stride 563)
         float* __restrict__ out_pred, float* __restrict__ out_mc) {
    __shared__ float As[16*68];
    __shared__ float Bs[16*64];
    const int tid = threadIdx.x;
    const int m0 = blockIdx.x << 6;       // 1024 blocks cover 65536 bt rows
    const int ar = tid >> 2, ac = (tid & 3) << 2;
    const int bk = tid >> 4, bn = (tid & 15) << 2;
    const int ty = tid >> 4, tx = tid & 15;
    float4 acc0 = make_float4(0,0,0,0), acc1 = acc0, acc2 = acc0, acc3 = acc0;
    const long arow = (long)(m0 + ar)*563;
    for (int k0 = 0; k0 < 512; k0 += 16) {
        As[(ac+0)*68 + ar] = __ldg(&mc_h[arow + k0 + ac + 0]);
        As[(ac+1)*68 + ar] = __ldg(&mc_h[arow + k0 + ac + 1]);
        As[(ac+2)*68 + ar] = __ldg(&mc_h[arow + k0 + ac + 2]);
        As[(ac+3)*68 + ar] = __ldg(&mc_h[arow + k0 + ac + 3]);
        *(float4*)(Bs + bk*64 + bn) = *(const float4*)(g_decWp + (k0 + bk)*64 + bn);
        __syncthreads();
        #pragma unroll
        for (int kk = 0; kk < 16; kk++) {
            float4 a = *(const float4*)(As + kk*68 + (ty << 2));
            float4 b = *(const float4*)(Bs + kk*64 + (tx << 2));
            acc0.x += a.x*b.x; acc0.y += a.x*b.y; acc0.z += a.x*b.z; acc0.w += a.x*b.w;
            acc1.x += a.y*b.x; acc1.y += a.y*b.y; acc1.z += a.y*b.z; acc1.w += a.y*b.w;
            acc2.x += a.z*b.x; acc2.y += a.z*b.y; acc2.z += a.z*b.z; acc2.w += a.z*b.w;
            acc3.x += a.w*b.x; acc3.y += a.w*b.y; acc3.z += a.w*b.z; acc3.w += a.w*b.w;
        }
        __syncthreads();
    }
    float4 accs[4] = {acc0, acc1, acc2, acc3};
    #pragma unroll
    for (int i = 0; i < 4; i++) {
        const long bt = m0 + (ty << 2) + i;
        #pragma unroll
        for (int j = 0; j < 4; j++) {
            int col = (tx << 2) + j;
            if (col < NJ3) {
                float v = ((j==0)?accs[i].x:(j==1)?accs[i].y:(j==2)?accs[i].z:accs[i].w)
                        + g_decbp[col];
                out_pred[bt*NJ3 + col] = v;
                out_mc[bt*563 + 512 + col] = v;
            }
        }
    }
}

// ---------------- entry ----------------
extern "C" void kernel_launch(void* const* d_in, const int* in_sizes, int n_in,
                              void* d_out, int out_size) {
    const float* x       = (const float*)d_in[0];
    const float* init_   = (const float*)d_in[1];
    const float* embed_W = (const float*)d_in[2];
    const float* embed_b = (const float*)d_in[3];
    const float* ni_W1   = (const float*)d_in[4];
    const float* ni_b1   = (const float*)d_in[5];
    const float* ni_W2   = (const float*)d_in[6];
    const float* ni_b2   = (const float*)d_in[7];
    const float* ni_W3   = (const float*)d_in[8];
    const float* ni_b3   = (const float*)d_in[9];
    const float* Wih0    = (const float*)d_in[10];
    const float* Whh0    = (const float*)d_in[11];
    const float* bih0    = (const float*)d_in[12];
    const float* bhh0    = (const float*)d_in[13];
    const float* Wih1    = (const float*)d_in[14];
    const float* Whh1    = (const float*)d_in[15];
    const float* bih1    = (const float*)d_in[16];
    const float* bhh1    = (const float*)d_in[17];
    const float* dec_W   = (const float*)d_in[18];
    const float* dec_b   = (const float*)d_in[19];

    float* out_pred = (float*)d_out;                              // (256,256,17,3)
    float* out_mc   = out_pred + (long)BATCH*FRAMES*NJ3;          // (256,256,563)

    k_setup_heavy<<<592, 256>>>(embed_W, embed_b, Wih0, bih0, bhh0, dec_W, dec_b);
    k_setup_copy <<<2048, 256>>>(x, init_, Wih0, Whh0, Wih1, Whh1, bih1, bhh1, ni_W1,
                                 dec_W, dec_b);
    k_persist    <<<GRID, THREADS>>>(x, ni_W2, ni_W3, ni_b1, ni_b2, ni_b3, out_mc);
    k_decode     <<<1024, 256>>>(out_mc, out_pred, out_mc);
}

// round 12
// speedup vs baseline: 2.3042x; 1.0444x over previous
#include <cuda_runtime.h>
#include <cuda_bf16.h>

// ---------------- problem constants ----------------
#define BATCH 256
#define FRAMES 256
#define IN_DIM 34
#define NJ3 51
#define DDIM 512
#define G4 2048            // 4*D
#define K0 576             // 34 x | 512 h0 | 30 pad
#define K1 1024            // 512 h0n | 512 h1prev
#define GRID 128
#define THREADS 256
#define NT (GRID*THREADS)
#define STG_HALVES 5376    // per-stage smem halves: Ah 1536 | Al 1536 | Wh 1152 | Wl 1152
#define STG_BYTES 10752

typedef unsigned short ushort_t;

// ---------------- PTX helpers ----------------
#define LDSM4(R, addr) asm volatile( \
    "ldmatrix.sync.aligned.m8n8.x4.shared.b16 {%0,%1,%2,%3},[%4];" \
    : "=r"((R)[0]),"=r"((R)[1]),"=r"((R)[2]),"=r"((R)[3]) : "r"(addr))
#define LDSM4T(R, addr) asm volatile( \
    "ldmatrix.sync.aligned.m8n8.x4.trans.shared.b16 {%0,%1,%2,%3},[%4];" \
    : "=r"((R)[0]),"=r"((R)[1]),"=r"((R)[2]),"=r"((R)[3]) : "r"(addr))
#define MMA_BF16(D, A, b0, b1) asm volatile( \
    "mma.sync.aligned.m16n8k16.row.col.f32.bf16.bf16.f32 " \
    "{%0,%1,%2,%3},{%4,%5,%6,%7},{%8,%9},{%0,%1,%2,%3};" \
    : "+f"((D)[0]),"+f"((D)[1]),"+f"((D)[2]),"+f"((D)[3]) \
    : "r"((A)[0]),"r"((A)[1]),"r"((A)[2]),"r"((A)[3]),"r"(b0),"r"(b1))
#define CP_ASYNC16(dst, src) asm volatile( \
    "cp.async.cg.shared.global [%0], [%1], 16;" :: "r"(dst), "l"(src))
#define CP_COMMIT() asm volatile("cp.async.commit_group;")
#define CP_WAIT2()  asm volatile("cp.async.wait_group 2;")

__device__ __forceinline__ void st_cg_u16(ushort_t* p, ushort_t v) {
    asm volatile("st.global.cg.u16 [%0], %1;" :: "l"(p), "h"(v));
}
__device__ __forceinline__ void bsplit(float v, ushort_t& hi, ushort_t& lo) {
    __nv_bfloat16 h = __float2bfloat16(v);
    __nv_bfloat16 l2 = __float2bfloat16(v - __bfloat162float(h));
    hi = *(ushort_t*)&h; lo = *(ushort_t*)&l2;
}

// ---------------- device scratch ----------------
// Gate-interleaved weights, split bf16: column m' = 4*d + gate (0=i,1=f,2=g,3=o)
__device__ ushort_t g_W0h[K0*G4];
__device__ ushort_t g_W0l[K0*G4];
__device__ ushort_t g_W1h[K1*G4];
__device__ ushort_t g_W1l[K1*G4];
__device__ float g_bias0[G4];         // includes decb@Wp fold
__device__ float g_bias1[G4];
__device__ float g_initp[BATCH*96];
__device__ float g_niW1p[96*DDIM];
__device__ float g_z1[BATCH*DDIM];
__device__ float g_z2[BATCH*1024];
__device__ float g_z3[BATCH*2048];
__device__ float g_decWp[512*64];     // decW padded 51->64 cols (fp32)
__device__ float g_decbp[64];
__device__ float g_WpT[NJ3*G4];       // Wp[j][m'] = Wih0[m][512+j], gate-interleaved cols (fp32)
__device__ float g_pred[2][BATCH*64]; // predc = pred - decb accumulators (fp32, padded 64)
// Ping-pong activations, split bf16
__device__ ushort_t g_X0h[2][BATCH*K0];
__device__ ushort_t g_X0l[2][BATCH*K0];
__device__ ushort_t g_X1h[2][BATCH*K1];
__device__ ushort_t g_X1l[2][BATCH*K1];
__device__ float g_c0[BATCH*DDIM];
__device__ float g_c1[BATCH*DDIM];

// barrier state: one global (init phase) + 4 per-group (scan)
__device__ unsigned int g_arrive;
__device__ volatile unsigned int g_release;
__device__ unsigned int g_garr[4];
__device__ volatile unsigned int g_grel[4];

__device__ __forceinline__ void grid_sync() {
    __threadfence();
    __syncthreads();
    if (threadIdx.x == 0) {
        unsigned int gen = g_release;
        unsigned int prev = atomicAdd(&g_arrive, 1u);
        if (prev == gridDim.x - 1u) {
            g_arrive = 0u;
            __threadfence();
            g_release = gen + 1u;
        } else {
            while (g_release == gen) { __nanosleep(32); }
        }
        __threadfence();
    }
    __syncthreads();
}

// scan barrier: only the 32 CTAs of one batch-group (batch dim fully partitions the scan)
__device__ __forceinline__ void group_sync(int g) {
    __threadfence();
    __syncthreads();
    if (threadIdx.x == 0) {
        unsigned int gen = g_grel[g];
        unsigned int prev = atomicAdd(&g_garr[g], 1u);
        if (prev == 31u) {
            g_garr[g] = 0u;
            __threadfence();
            g_grel[g] = gen + 1u;
        } else {
            while (g_grel[g] == gen) { __nanosleep(32); }
        }
        __threadfence();
    }
    __syncthreads();
}

__device__ __forceinline__ float sigf(float v)  { return 1.0f / (1.0f + __expf(-v)); }
__device__ __forceinline__ float tanhg(float v) { float e = __expf(2.0f*v); return 1.0f - 2.0f/(e + 1.0f); }

// ---------------- setup kernel 1: folded x-weight + bias0 ----------------
__global__ void k_setup_heavy(const float* __restrict__ embed_W,
                              const float* __restrict__ embed_b,
                              const float* __restrict__ Wih0,
                              const float* __restrict__ bih0,
                              const float* __restrict__ bhh0,
                              const float* __restrict__ decb) {
    int idx = blockIdx.x * blockDim.x + threadIdx.x;
    const int TOT = 35*G4;
    for (; idx < TOT; idx += gridDim.x * blockDim.x) {
        if (idx < 34*G4) {                               // rows 0..33: embed fold
            int m = idx & 2047, j = idx >> 11;
            int mp = ((m & 511) << 2) | (m >> 9);
            const float* wr = Wih0 + m*563;
            const float* er = embed_W + j*512;
            float s = 0.f;
            #pragma unroll 4
            for (int d = 0; d < 512; d++) s += er[d] * wr[d];
            ushort_t hi, lo; bsplit(s, hi, lo);
            g_W0h[j*G4 + mp] = hi; g_W0l[j*G4 + mp] = lo;
        } else {                                         // bias0 = bih0+bhh0+embed_b@Wx^T+decb@Wp
            int m = idx - 34*G4;
            int mp = ((m & 511) << 2) | (m >> 9);
            const float* wr = Wih0 + m*563;
            float s = bih0[m] + bhh0[m];
            #pragma unroll 4
            for (int d = 0; d < 512; d++) s += embed_b[d] * wr[d];
            for (int j = 0; j < NJ3; j++) s += decb[j] * wr[512 + j];
            g_bias0[mp] = s;
        }
    }
}

// ---------------- setup kernel 2: packs/copies ----------------
__global__ void k_setup_copy(const float* __restrict__ x,
                             const float* __restrict__ init,
                             const float* __restrict__ Wih0,
                             const float* __restrict__ Whh0,
                             const float* __restrict__ Wih1,
                             const float* __restrict__ Whh1,
                             const float* __restrict__ bih1,
                             const float* __restrict__ bhh1,
                             const float* __restrict__ niW1,
                             const float* __restrict__ decW,
                             const float* __restrict__ decb) {
    const int S1  = 512*G4;           // W0 rows 34..545 (Whh0)
    const int S1b = 30*G4;            // W0 pad rows 546..575
    const int S2  = 1024*G4;          // W1
    const int S3  = G4;               // bias1
    const int S4  = BATCH*96;         // initp
    const int S5  = 96*DDIM;          // niW1p
    const int S6  = BATCH*IN_DIM;     // X0[0] cols 0..33 (x_0)
    const int S6b = BATCH*128;        // g_pred[0] (pred0-decb) + g_pred[1] (zero)
    const int S7  = BATCH*60;         // X0 pad cols 546..575, both buffers
    const int S8  = 512*64 + 64;      // decWp + decbp
    const int S9  = NJ3*G4;           // WpT
    const int TOT = S1+S1b+S2+S3+S4+S5+S6+S6b+S7+S8+S9;
    int i = blockIdx.x * blockDim.x + threadIdx.x;
    for (; i < TOT; i += gridDim.x * blockDim.x) {
        int r = i;
        if (r < S1) {
            int m = r & 2047; int k = 34 + (r >> 11);
            int mp = ((m & 511) << 2) | (m >> 9);
            float v = Whh0[m*512 + (k-34)];
            ushort_t hi, lo; bsplit(v, hi, lo);
            g_W0h[k*G4 + mp] = hi; g_W0l[k*G4 + mp] = lo;
            continue;
        }
        r -= S1;
        if (r < S1b) {
            int m = r & 2047; int k = 546 + (r >> 11);
            int mp = ((m & 511) << 2) | (m >> 9);
            g_W0h[k*G4 + mp] = 0; g_W0l[k*G4 + mp] = 0;
            continue;
        }
        r -= S1b;
        if (r < S2) {
            int m = r & 2047; int k = r >> 11;
            int mp = ((m & 511) << 2) | (m >> 9);
            float v = (k < 512) ? Wih1[m*512 + k] : Whh1[m*512 + (k-512)];
            ushort_t hi, lo; bsplit(v, hi, lo);
            g_W1h[k*G4 + mp] = hi; g_W1l[k*G4 + mp] = lo;
            continue;
        }
        r -= S2;
        if (r < S3) {
            int mp = ((r & 511) << 2) | (r >> 9);
            g_bias1[mp] = bih1[r] + bhh1[r]; continue;
        }
        r -= S3;
        if (r < S4) { int b = r/96, j = r - b*96; g_initp[r] = (j < 85) ? init[b*85 + j] : 0.f; continue; }
        r -= S4;
        if (r < S5) { int k = r >> 9;  g_niW1p[r] = (k < 85) ? niW1[r] : 0.f; continue; }
        r -= S5;
        if (r < S6) {
            int b = r/IN_DIM, j = r - b*IN_DIM;
            ushort_t hi, lo; bsplit(x[(b*FRAMES)*IN_DIM + j], hi, lo);
            g_X0h[0][b*K0 + j] = hi; g_X0l[0][b*K0 + j] = lo;
            continue;
        }
        r -= S6;
        if (r < S6b) {
            int b = r >> 7, z = r & 127;
            int buf = z >> 6, j = z & 63;
            float v = 0.f;
            if (buf == 0 && j < NJ3) v = init[b*85 + j] - decb[j];   // predc_0 = pred0 - decb  [FIX: pred0 = init[:, :NJ3]]
            g_pred[buf][b*64 + j] = v;
            continue;
        }
        r -= S6b;
        if (r < S7) {
            int b = r/60, z = r - b*60;
            int buf = z/30, col = 546 + (z%30);
            g_X0h[buf][b*K0 + col] = 0; g_X0l[buf][b*K0 + col] = 0;
            continue;
        }
        r -= S7;
        if (r < 512*64 + 64) {
            if (r < 512*64) { int k = r >> 6, j = r & 63; g_decWp[r] = (j < NJ3) ? decW[k*NJ3 + j] : 0.f; }
            else { int j = r - 512*64; g_decbp[j] = (j < NJ3) ? decb[j] : 0.f; }
            continue;
        }
        r -= S8;
        {   // WpT[j][mp] = Wih0[m][512+j]
            int m = r & 2047, j = r >> 11;
            int mp = ((m & 511) << 2) | (m >> 9);
            g_WpT[j*G4 + mp] = Wih0[m*563 + 512 + j];
        }
    }
}

// ---------------- generic tiled GEMM (init MLP only; fp32 scalar) -----------
template<bool RELU>
__device__ __forceinline__ void gemm_nt(const float* __restrict__ A, int lda,
                                        const float* __restrict__ B, int ldb,
                                        float* __restrict__ C, int ldc,
                                        int M, int N, int K,
                                        const float* __restrict__ bias,
                                        float* sm) {
    float* As = sm;             // [16][68]
    float* Bs = sm + 16*68;     // [16][64]
    const int tid = threadIdx.x;
    const int nT = N >> 6;
    const int ntiles = (M >> 6) * nT;
    const int ar = tid >> 2, ac = (tid & 3) << 2;
    const int bk = tid >> 4, bn = (tid & 15) << 2;
    const int ty = tid >> 4, tx = tid & 15;
    for (int tile = blockIdx.x; tile < ntiles; tile += gridDim.x) {
        const int m0 = (tile / nT) << 6;
        const int n0 = (tile - (tile / nT) * nT) << 6;
        float4 acc0 = make_float4(0,0,0,0), acc1 = acc0, acc2 = acc0, acc3 = acc0;
        for (int k0 = 0; k0 < K; k0 += 16) {
            float4 va = __ldcg((const float4*)(A + (m0 + ar)*lda + k0 + ac));
            float4 vb = __ldg ((const float4*)(B + (k0 + bk)*ldb + n0 + bn));
            As[(ac+0)*68 + ar] = va.x;
            As[(ac+1)*68 + ar] = va.y;
            As[(ac+2)*68 + ar] = va.z;
            As[(ac+3)*68 + ar] = va.w;
            *(float4*)(Bs + bk*64 + bn) = vb;
            __syncthreads();
            #pragma unroll
            for (int kk = 0; kk < 16; kk++) {
                float4 a = *(const float4*)(As + kk*68 + (ty << 2));
                float4 b = *(const float4*)(Bs + kk*64 + (tx << 2));
                acc0.x += a.x*b.x; acc0.y += a.x*b.y; acc0.z += a.x*b.z; acc0.w += a.x*b.w;
                acc1.x += a.y*b.x; acc1.y += a.y*b.y; acc1.z += a.y*b.z; acc1.w += a.y*b.w;
                acc2.x += a.z*b.x; acc2.y += a.z*b.y; acc2.z += a.z*b.z; acc2.w += a.z*b.w;
                acc3.x += a.w*b.x; acc3.y += a.w*b.y; acc3.z += a.w*b.z; acc3.w += a.w*b.w;
            }
            __syncthreads();
        }
        float4 bb = __ldg((const float4*)(bias + n0 + (tx << 2)));
        float4 accs[4] = {acc0, acc1, acc2, acc3};
        #pragma unroll
        for (int i = 0; i < 4; i++) {
            float4 v = accs[i];
            v.x += bb.x; v.y += bb.y; v.z += bb.z; v.w += bb.w;
            if (RELU) { v.x = fmaxf(v.x, 0.f); v.y = fmaxf(v.y, 0.f);
                        v.z = fmaxf(v.z, 0.f); v.w = fmaxf(v.w, 0.f); }
            __stcg((float4*)(C + (m0 + (ty << 2) + i)*ldc + n0 + (tx << 2)), v);
        }
    }
}

// ---------------- fused MMA GEMM + LSTM-cell epilogue (4-stage cp.async) --------------
// LAYER 0: + fp32 pred@Wp correction in epilogue, zeroes g_pred[nxt] (n-tile 0 CTA).
// LAYER 1: + fp32 h1@decW partials atomicAdd'ed into g_pred[nxt].
template<int LAYER>
__device__ __forceinline__ void gemm_cell_mma(
    const ushort_t* __restrict__ Ah, const ushort_t* __restrict__ Al, int K,
    const ushort_t* __restrict__ Wh, const ushort_t* __restrict__ Wl,
    const float* __restrict__ bias,
    float* __restrict__ cArr,
    ushort_t* __restrict__ X0nh, ushort_t* __restrict__ X0nl,
    ushort_t* __restrict__ X1ah, ushort_t* __restrict__ X1al,   // layer0: X1cur; layer1: X1next
    const float* __restrict__ predCur, float* __restrict__ predNxt,
    float* __restrict__ out_mc, int t,
    ushort_t* sm)
{
    const int tid = threadIdx.x;
    const int l = tid & 31, w = tid >> 5;
    const int wm = w >> 2, wn = w & 3;
    const int m0 = (blockIdx.x >> 5) << 6;
    const int n0 = (blockIdx.x & 31) << 6;

    // cp.async staging mapping (2 x 16B per thread)
    const int hl  = tid >> 7;
    const int a_r = (tid >> 1) & 63, a_c = (tid & 1) << 3;
    const int w_r = (tid >> 3) & 15, w_c = (tid & 7) << 3;
    const unsigned int a_dst = (hl*1536 + a_r*24 + a_c) * 2;
    const unsigned int w_dst = (3072 + hl*1152 + w_r*72 + w_c) * 2;
    const ushort_t* a_src = (hl ? Al : Ah) + (m0 + a_r)*K + a_c;
    const ushort_t* w_src = (hl ? Wl : Wh) + (long)w_r*G4 + n0 + w_c;

    const unsigned int smb = (unsigned int)__cvta_generic_to_shared(sm);

    float D[2][2][4];
    #pragma unroll
    for (int a = 0; a < 2; a++)
        #pragma unroll
        for (int b = 0; b < 2; b++)
            #pragma unroll
            for (int k = 0; k < 4; k++) D[a][b][k] = 0.f;

    const int NC = K >> 4;

    // prologue: issue chunks 0..2
    #pragma unroll
    for (int s = 0; s < 3; s++) {
        unsigned int base = smb + s*STG_BYTES;
        CP_ASYNC16(base + a_dst, a_src + (s << 4));
        CP_ASYNC16(base + w_dst, w_src + ((long)(s << 4))*G4);
        CP_COMMIT();
    }

    // lane addresses for LDSM (byte offsets within a stage)
    const unsigned int a_off = wm*1536 + (l & 15)*48 + (l >> 4)*16;
    const unsigned int b_off = 6144 + ((l & 7) + ((l >> 3) & 1)*8)*144
                             + (wn*16 + (l >> 4)*8)*2;

    for (int kc = 0; kc < NC; kc++) {
        CP_WAIT2();
        __syncthreads();
        if (kc + 3 < NC) {
            unsigned int base = smb + ((kc + 3) & 3)*STG_BYTES;
            CP_ASYNC16(base + a_dst, a_src + ((kc + 3) << 4));
            CP_ASYNC16(base + w_dst, w_src + ((long)((kc + 3) << 4))*G4);
        }
        CP_COMMIT();

        const unsigned int bb = smb + (kc & 3)*STG_BYTES;
        unsigned int ah0[4], ah1[4], al0[4], al1[4], bh[4], bl[4];
        LDSM4 (ah0, bb + a_off);
        LDSM4 (ah1, bb + a_off + 768);
        LDSM4 (al0, bb + a_off + 3072);
        LDSM4 (al1, bb + a_off + 3072 + 768);
        LDSM4T(bh,  bb + b_off);
        LDSM4T(bl,  bb + b_off + 2304);
        // 12 MMAs: hi*hi, hi*lo, lo*hi
        MMA_BF16(D[0][0], ah0, bh[0], bh[1]); MMA_BF16(D[0][1], ah0, bh[2], bh[3]);
        MMA_BF16(D[1][0], ah1, bh[0], bh[1]); MMA_BF16(D[1][1], ah1, bh[2], bh[3]);
        MMA_BF16(D[0][0], ah0, bl[0], bl[1]); MMA_BF16(D[0][1], ah0, bl[2], bl[3]);
        MMA_BF16(D[1][0], ah1, bl[0], bl[1]); MMA_BF16(D[1][1], ah1, bl[2], bl[3]);
        MMA_BF16(D[0][0], al0, bh[0], bh[1]); MMA_BF16(D[0][1], al0, bh[2], bh[3]);
        MMA_BF16(D[1][0], al1, bh[0], bh[1]); MMA_BF16(D[1][1], al1, bh[2], bh[3]);
    }

    // ---- epilogue ----
    const int tig = l & 3, r = l >> 2;
    const int nw = n0 + wn*16;
    const int mw = m0 + wm*32;
    const int nf0dd = (nw >> 2);                 // per-thread dd computed below

    float* smf = (float*)sm;
    float4 corr[2][2];
    #pragma unroll
    for (int a2 = 0; a2 < 2; a2++)
        #pragma unroll
        for (int b2 = 0; b2 < 2; b2++) corr[a2][b2] = make_float4(0,0,0,0);

    const int ddl_t = (wn*4) + (tig & 1)*2 + (tig >> 1);   // local dd 0..15

    if (LAYER == 0) {
        // stage pred tile [64][52] + Wp slice [51][64]; zero predNxt (n-tile-0 CTA)
        __syncthreads();                 // all cp.async/LDSM done; smem reusable
        float* preds = smf;              // 64*52
        float* wps   = smf + 64*52;      // 51*64
        for (int i = tid; i < 64*52; i += THREADS) {
            int b2 = i/52, j = i - b2*52;
            preds[i] = (j < NJ3) ? __ldcg(&predCur[(m0 + b2)*64 + j]) : 0.f;
        }
        for (int i = tid; i < NJ3*64; i += THREADS)
            wps[i] = __ldg(&g_WpT[(i >> 6)*G4 + n0 + (i & 63)]);
        if ((blockIdx.x & 31) == 0)
            for (int i = tid; i < 64*64; i += THREADS)
                __stcg(&predNxt[(m0 + (i >> 6))*64 + (i & 63)], 0.f);
        __syncthreads();
        // correction = predc @ Wp  (per thread: 4 b x (i,f,g,o) of dd_t)
        for (int j = 0; j < NJ3; j++) {
            float4 w4 = *(const float4*)(wps + j*64 + 4*ddl_t);
            #pragma unroll
            for (int mf = 0; mf < 2; mf++)
                #pragma unroll
                for (int rr = 0; rr < 2; rr++) {
                    float p = preds[(wm*32 + mf*16 + r + rr*8)*52 + j];
                    corr[mf][rr].x += p*w4.x; corr[mf][rr].y += p*w4.y;
                    corr[mf][rr].z += p*w4.z; corr[mf][rr].w += p*w4.w;
                }
        }
    }

    float* hs = smf;                 // [64][17]  (LAYER 1)
    float* ds = smf + 64*17;         // [16][52]
    if (LAYER == 1) {
        __syncthreads();             // smem reusable
        for (int i = tid; i < 16*52; i += THREADS) {
            int dl = i/52, j = i - dl*52;
            ds[i] = (j < NJ3) ? __ldg(&g_decWp[((n0 >> 2) + dl)*64 + j]) : 0.f;
        }
        __syncthreads();
    }

    // LSTM cell on (i,f,g,o) quads via pair shuffle
    #pragma unroll
    for (int mf = 0; mf < 2; mf++) {
        float oth[4];
        #pragma unroll
        for (int k = 0; k < 4; k++) {
            float send = (tig & 1) ? D[mf][0][k] : D[mf][1][k];
            oth[k] = __shfl_xor_sync(0xffffffffu, send, 1);
        }
        const int nf = (tig & 1);
        const int dd = nf0dd + nf*2 + (tig >> 1);
        const float4 bb4 = __ldg((const float4*)(bias + 4*dd));
        float iv[2], fv[2], gv[2], ov[2];
        if (!nf) {
            iv[0] = D[mf][0][0]; fv[0] = D[mf][0][1]; gv[0] = oth[0]; ov[0] = oth[1];
            iv[1] = D[mf][0][2]; fv[1] = D[mf][0][3]; gv[1] = oth[2]; ov[1] = oth[3];
        } else {
            iv[0] = oth[0]; fv[0] = oth[1]; gv[0] = D[mf][1][0]; ov[0] = D[mf][1][1];
            iv[1] = oth[2]; fv[1] = oth[3]; gv[1] = D[mf][1][2]; ov[1] = D[mf][1][3];
        }
        #pragma unroll
        for (int rr = 0; rr < 2; rr++) {
            const int b = mw + mf*16 + r + rr*8;
            float ig = sigf (iv[rr] + bb4.x + corr[mf][rr].x);
            float fg = sigf (fv[rr] + bb4.y + corr[mf][rr].y);
            float gg = tanhg(gv[rr] + bb4.z + corr[mf][rr].z);
            float og = sigf (ov[rr] + bb4.w + corr[mf][rr].w);
            float c  = fg * cArr[b*DDIM + dd] + ig * gg;   // CTA-private
            cArr[b*DDIM + dd] = c;
            float h = og * tanhg(c);
            ushort_t hh, hl2; bsplit(h, hh, hl2);
            if (LAYER == 0) {
                st_cg_u16(&X1ah[b*K1 + dd], hh);           // gates1 input (this step)
                st_cg_u16(&X1al[b*K1 + dd], hl2);
                st_cg_u16(&X0nh[b*K0 + 34 + dd], hh);      // recurrent h0 (next step)
                st_cg_u16(&X0nl[b*K0 + 34 + dd], hl2);
            } else {
                st_cg_u16(&X1ah[b*K1 + 512 + dd], hh);     // recurrent h1 (next step)
                st_cg_u16(&X1al[b*K1 + 512 + dd], hl2);
                out_mc[((long)b*FRAMES + t)*563 + dd] = h; // motion_context h part (fp32)
                hs[(b - m0)*17 + (dd - (n0 >> 2))] = h;    // for pred partials
            }
        }
    }

    if (LAYER == 1) {
        // pred partials: h1_tile @ decW_slice -> atomicAdd into predNxt
        __syncthreads();
        for (int i = tid; i < 64*NJ3; i += THREADS) {
            int lb = i/NJ3, j = i - lb*NJ3;
            float s = 0.f;
            #pragma unroll
            for (int dl = 0; dl < 16; dl++) s += hs[lb*17 + dl] * ds[dl*52 + j];
            atomicAdd(&predNxt[(m0 + lb)*64 + j], s);
        }
    }
}

// ---------------- persistent scan kernel ----------------
__global__ void __launch_bounds__(THREADS, 1)
k_persist(const float* __restrict__ x,
          const float* __restrict__ niW2, const float* __restrict__ niW3,
          const float* __restrict__ nb1,  const float* __restrict__ nb2,
          const float* __restrict__ nb3,
          float* __restrict__ out_mc) {
    __shared__ __align__(16) ushort_t smem[4*STG_HALVES];   // 43 KB
    float* smf = (float*)smem;
    const int gtid = blockIdx.x * THREADS + threadIdx.x;
    const int grp = blockIdx.x >> 5;

    // ---- init network (fp32 scalar path; runs once; global barriers) ----
    gemm_nt<true >(g_initp, 96,   g_niW1p, DDIM, g_z1, DDIM, BATCH, DDIM, 96,   nb1, smf);
    grid_sync();
    gemm_nt<true >(g_z1,   DDIM,  niW2,    1024, g_z2, 1024, BATCH, 1024, DDIM, nb2, smf);
    grid_sync();
    gemm_nt<false>(g_z2,   1024,  niW3,    2048, g_z3, 2048, BATCH, 2048, 1024, nb3, smf);
    grid_sync();
    for (int idx = gtid; idx < BATCH*DDIM; idx += NT) {
        int b = idx >> 9, d = idx & 511;
        const float* zr = g_z3 + b*2048;
        ushort_t hi, lo;
        bsplit(__ldcg(zr + d), hi, lo);                       // h0 init
        st_cg_u16(&g_X0h[0][b*K0 + 34 + d], hi); st_cg_u16(&g_X0l[0][b*K0 + 34 + d], lo);
        bsplit(__ldcg(zr + 512 + d), hi, lo);                 // h1 init
        st_cg_u16(&g_X1h[0][b*K1 + 512 + d], hi); st_cg_u16(&g_X1l[0][b*K1 + 512 + d], lo);
        __stcg(&g_c0[idx], __ldcg(zr + 1024 + d));
        __stcg(&g_c1[idx], __ldcg(zr + 1536 + d));
    }
    grid_sync();

    // ---- scan: 2 group syncs per step (batch dim partitions into 4 groups) ----
    for (int t = 0; t < FRAMES; t++) {
        const int cur = t & 1, nxt = cur ^ 1;

        // phase A: gates0 MMA GEMM (K=576) + pred@Wp correction + cell0 epilogue
        gemm_cell_mma<0>(g_X0h[cur], g_X0l[cur], K0, g_W0h, g_W0l, g_bias0, g_c0,
                         g_X0h[nxt], g_X0l[nxt], g_X1h[cur], g_X1l[cur],
                         g_pred[cur], g_pred[nxt], nullptr, t, smem);
        group_sync(grp);

        // phase B: gates1 MMA GEMM + cell1 epilogue + pred partial accumulation
        gemm_cell_mma<1>(g_X1h[cur], g_X1l[cur], K1, g_W1h, g_W1l, g_bias1, g_c1,
                         nullptr, nullptr, g_X1h[nxt], g_X1l[nxt],
                         nullptr, g_pred[nxt], out_mc, t, smem);

        // x_{t+1} copy (one CTA per group; 64 rows)
        if ((blockIdx.x & 31) == 0 && t + 1 < FRAMES) {
            const int mbase = grp << 6;
            for (int i = threadIdx.x; i < 64*IN_DIM; i += THREADS) {
                int rr = i / IN_DIM, j = i - rr*IN_DIM;
                int b = mbase + rr;
                float v = __ldg(&x[((long)b*FRAMES + t + 1)*IN_DIM + j]);
                ushort_t hi, lo; bsplit(v, hi, lo);
                st_cg_u16(&g_X0h[nxt][b*K0 + j], hi);
                st_cg_u16(&g_X0l[nxt][b*K0 + j], lo);
            }
        }
        group_sync(grp);
    }
}

// ---------------- post-scan decoder: preds = H1_all @ decW + decb ----------------
__global__ void __launch_bounds__(256)
k_decode(const float* __restrict__ mc_h,   // out_mc (h part, cols 0..511, stride 563)
         float* __restrict__ out_pred, float* __restrict__ out_mc) {
    __shared__ float As[16*68];
    __shared__ float Bs[16*64];
    const int tid = threadIdx.x;
    const int m0 = blockIdx.x << 6;       // 1024 blocks cover 65536 bt rows
    const int ar = tid >> 2, ac = (tid & 3) << 2;
    const int bk = tid >> 4, bn = (tid & 15) << 2;
    const int ty = tid >> 4, tx = tid & 15;
    float4 acc0 = make_float4(0,0,0,0), acc1 = acc0, acc2 = acc0, acc3 = acc0;
    const long arow = (long)(m0 + ar)*563;
    for (int k0 = 0; k0 < 512; k0 += 16) {
        As[(ac+0)*68 + ar] = __ldg(&mc_h[arow + k0 + ac + 0]);
        As[(ac+1)*68 + ar] = __ldg(&mc_h[arow + k0 + ac + 1]);
        As[(ac+2)*68 + ar] = __ldg(&mc_h[arow + k0 + ac + 2]);
        As[(ac+3)*68 + ar] = __ldg(&mc_h[arow + k0 + ac + 3]);
        *(float4*)(Bs + bk*64 + bn) = *(const float4*)(g_decWp + (k0 + bk)*64 + bn);
        __syncthreads();
        #pragma unroll
        for (int kk = 0; kk < 16; kk++) {
            float4 a = *(const float4*)(As + kk*68 + (ty << 2));
            float4 b = *(const float4*)(Bs + kk*64 + (tx << 2));
            acc0.x += a.x*b.x; acc0.y += a.x*b.y; acc0.z += a.x*b.z; acc0.w += a.x*b.w;
            acc1.x += a.y*b.x; acc1.y += a.y*b.y; acc1.z += a.y*b.z; acc1.w += a.y*b.w;
            acc2.x += a.z*b.x; acc2.y += a.z*b.y; acc2.z += a.z*b.z; acc2.w += a.z*b.w;
            acc3.x += a.w*b.x; acc3.y += a.w*b.y; acc3.z += a.w*b.z; acc3.w += a.w*b.w;
        }
        __syncthreads();
    }
    float4 accs[4] = {acc0, acc1, acc2, acc3};
    #pragma unroll
    for (int i = 0; i < 4; i++) {
        const long bt = m0 + (ty << 2) + i;
        #pragma unroll
        for (int j = 0; j < 4; j++) {
            int col = (tx << 2) + j;
            if (col < NJ3) {
                float v = ((j==0)?accs[i].x:(j==1)?accs[i].y:(j==2)?accs[i].z:accs[i].w)
                        + g_decbp[col];
                out_pred[bt*NJ3 + col] = v;
                out_mc[bt*563 + 512 + col] = v;
            }
        }
    }
}

// ---------------- entry ----------------
extern "C" void kernel_launch(void* const* d_in, const int* in_sizes, int n_in,
                              void* d_out, int out_size) {
    const float* x       = (const float*)d_in[0];
    const float* init_   = (const float*)d_in[1];
    const float* embed_W = (const float*)d_in[2];
    const float* embed_b = (const float*)d_in[3];
    const float* ni_W1   = (const float*)d_in[4];
    const float* ni_b1   = (const float*)d_in[5];
    const float* ni_W2   = (const float*)d_in[6];
    const float* ni_b2   = (const float*)d_in[7];
    const float* ni_W3   = (const float*)d_in[8];
    const float* ni_b3   = (const float*)d_in[9];
    const float* Wih0    = (const float*)d_in[10];
    const float* Whh0    = (const float*)d_in[11];
    const float* bih0    = (const float*)d_in[12];
    const float* bhh0    = (const float*)d_in[13];
    const float* Wih1    = (const float*)d_in[14];
    const float* Whh1    = (const float*)d_in[15];
    const float* bih1    = (const float*)d_in[16];
    const float* bhh1    = (const float*)d_in[17];
    const float* dec_W   = (const float*)d_in[18];
    const float* dec_b   = (const float*)d_in[19];

    float* out_pred = (float*)d_out;                              // (256,256,17,3)
    float* out_mc   = out_pred + (long)BATCH*FRAMES*NJ3;          // (256,256,563)

    k_setup_heavy<<<280, 256>>>(embed_W, embed_b, Wih0, bih0, bhh0, dec_b);
    k_setup_copy <<<2048, 256>>>(x, init_, Wih0, Whh0, Wih1, Whh1, bih1, bhh1, ni_W1,
                                 dec_W, dec_b);
    k_persist    <<<GRID, THREADS>>>(x, ni_W2, ni_W3, ni_b1, ni_b2, ni_b3, out_mc);
    k_decode     <<<1024, 256>>>(out_mc, out_pred, out_mc);
}

// round 14
// speedup vs baseline: 2.7485x; 1.1928x over previous
#include <cuda_runtime.h>
#include <cuda_bf16.h>
#include <cuda_fp16.h>

// ---------------- problem constants ----------------
#define BATCH 256
#define FRAMES 256
#define IN_DIM 34
#define NJ3 51
#define DDIM 512
#define G4 2048            // 4*D
#define K0 576             // 34 x | 512 h0 (at col 34) | 30 pad
#define K1 1024            // 512 h0n | 512 h1prev
#define GRID 128
#define THREADS 256
#define NT (GRID*THREADS)
// fp16 single-precision stage: A[64][24] halves (3072B) | W[16][72] halves (2304B)
#define STG_HALVES 2688
#define STG_BYTES 5376

typedef unsigned short ushort_t;

// ---------------- PTX helpers ----------------
#define LDSM4(R, addr) asm volatile( \
    "ldmatrix.sync.aligned.m8n8.x4.shared.b16 {%0,%1,%2,%3},[%4];" \
    : "=r"((R)[0]),"=r"((R)[1]),"=r"((R)[2]),"=r"((R)[3]) : "r"(addr))
#define LDSM4T(R, addr) asm volatile( \
    "ldmatrix.sync.aligned.m8n8.x4.trans.shared.b16 {%0,%1,%2,%3},[%4];" \
    : "=r"((R)[0]),"=r"((R)[1]),"=r"((R)[2]),"=r"((R)[3]) : "r"(addr))
#define MMA_F16(D, A, b0, b1) asm volatile( \
    "mma.sync.aligned.m16n8k16.row.col.f32.f16.f16.f32 " \
    "{%0,%1,%2,%3},{%4,%5,%6,%7},{%8,%9},{%0,%1,%2,%3};" \
    : "+f"((D)[0]),"+f"((D)[1]),"+f"((D)[2]),"+f"((D)[3]) \
    : "r"((A)[0]),"r"((A)[1]),"r"((A)[2]),"r"((A)[3]),"r"(b0),"r"(b1))
#define CP_ASYNC16(dst, src) asm volatile( \
    "cp.async.cg.shared.global [%0], [%1], 16;" :: "r"(dst), "l"(src))
#define CP_COMMIT() asm volatile("cp.async.commit_group;")
#define CP_WAIT2()  asm volatile("cp.async.wait_group 2;")

__device__ __forceinline__ void st_cg_u16(ushort_t* p, ushort_t v) {
    asm volatile("st.global.cg.u16 [%0], %1;" :: "l"(p), "h"(v));
}
__device__ __forceinline__ ushort_t f16b(float v) {
    __half h = __float2half(v);
    return *(ushort_t*)&h;
}

// ---------------- device scratch ----------------
// Gate-interleaved weights, fp16, K-major [k][m']: m' = 4*d + gate (0=i,1=f,2=g,3=o)
__device__ ushort_t g_W0[K0*G4];
__device__ ushort_t g_W1[K1*G4];
__device__ float g_bias0[G4];         // includes decb@Wp fold
__device__ float g_bias1[G4];
__device__ float g_initp[BATCH*96];
__device__ float g_niW1p[96*DDIM];
__device__ float g_z1[BATCH*DDIM];
__device__ float g_z2[BATCH*1024];
__device__ float g_z3[BATCH*2048];
__device__ float g_decWp[512*64];     // decW padded 51->64 cols (fp32)
__device__ float g_decbp[64];
__device__ float g_WpT[NJ3*G4];       // Wp[j][m'] = Wih0[m][512+j], gate-interleaved cols (fp32)
__device__ float g_pred[2][BATCH*64]; // predc = pred - decb accumulators (fp32, padded 64)
// Ping-pong activations, fp16
__device__ ushort_t g_X0[2][BATCH*K0];
__device__ ushort_t g_X1[2][BATCH*K1];
__device__ float g_c0[BATCH*DDIM];
__device__ float g_c1[BATCH*DDIM];

// barrier state: one global (init phase) + 4 per-group (scan)
__device__ unsigned int g_arrive;
__device__ volatile unsigned int g_release;
__device__ unsigned int g_garr[4];
__device__ volatile unsigned int g_grel[4];

__device__ __forceinline__ void grid_sync() {
    __threadfence();
    __syncthreads();
    if (threadIdx.x == 0) {
        unsigned int gen = g_release;
        unsigned int prev = atomicAdd(&g_arrive, 1u);
        if (prev == gridDim.x - 1u) {
            g_arrive = 0u;
            __threadfence();
            g_release = gen + 1u;
        } else {
            while (g_release == gen) { __nanosleep(32); }
        }
        __threadfence();
    }
    __syncthreads();
}

// scan barrier: only the 32 CTAs of one batch-group
__device__ __forceinline__ void group_sync(int g) {
    __threadfence();
    __syncthreads();
    if (threadIdx.x == 0) {
        unsigned int gen = g_grel[g];
        unsigned int prev = atomicAdd(&g_garr[g], 1u);
        if (prev == 31u) {
            g_garr[g] = 0u;
            __threadfence();
            g_grel[g] = gen + 1u;
        } else {
            while (g_grel[g] == gen) { __nanosleep(32); }
        }
        __threadfence();
    }
    __syncthreads();
}

__device__ __forceinline__ float sigf(float v)  { return 1.0f / (1.0f + __expf(-v)); }
__device__ __forceinline__ float tanhg(float v) { float e = __expf(2.0f*v); return 1.0f - 2.0f/(e + 1.0f); }

// ---------------- setup kernel 1: folded x-weight + bias0 ----------------
__global__ void k_setup_heavy(const float* __restrict__ embed_W,
                              const float* __restrict__ embed_b,
                              const float* __restrict__ Wih0,
                              const float* __restrict__ bih0,
                              const float* __restrict__ bhh0,
                              const float* __restrict__ decb) {
    int idx = blockIdx.x * blockDim.x + threadIdx.x;
    const int TOT = 35*G4;
    for (; idx < TOT; idx += gridDim.x * blockDim.x) {
        if (idx < 34*G4) {                               // rows 0..33: embed fold
            int m = idx & 2047, j = idx >> 11;
            int mp = ((m & 511) << 2) | (m >> 9);
            const float* wr = Wih0 + m*563;
            const float* er = embed_W + j*512;
            float s = 0.f;
            #pragma unroll 4
            for (int d = 0; d < 512; d++) s += er[d] * wr[d];
            g_W0[j*G4 + mp] = f16b(s);
        } else {                                         // bias0 = bih0+bhh0+embed_b@Wx^T+decb@Wp
            int m = idx - 34*G4;
            int mp = ((m & 511) << 2) | (m >> 9);
            const float* wr = Wih0 + m*563;
            float s = bih0[m] + bhh0[m];
            #pragma unroll 4
            for (int d = 0; d < 512; d++) s += embed_b[d] * wr[d];
            for (int j = 0; j < NJ3; j++) s += decb[j] * wr[512 + j];
            g_bias0[mp] = s;
        }
    }
}

// ---------------- setup kernel 2: packs/copies ----------------
__global__ void k_setup_copy(const float* __restrict__ x,
                             const float* __restrict__ init,
                             const float* __restrict__ Wih0,
                             const float* __restrict__ Whh0,
                             const float* __restrict__ Wih1,
                             const float* __restrict__ Whh1,
                             const float* __restrict__ bih1,
                             const float* __restrict__ bhh1,
                             const float* __restrict__ niW1,
                             const float* __restrict__ decW,
                             const float* __restrict__ decb) {
    const int S1  = 512*G4;           // W0 rows 34..545 (Whh0)
    const int S1b = 30*G4;            // W0 pad rows 546..575
    const int S2  = 1024*G4;          // W1
    const int S3  = G4;               // bias1
    const int S4  = BATCH*96;         // initp
    const int S5  = 96*DDIM;          // niW1p
    const int S6  = BATCH*IN_DIM;     // X0[0] cols 0..33 (x_0)
    const int S6b = BATCH*128;        // g_pred[0] (pred0-decb) + g_pred[1] (zero)
    const int S7  = BATCH*60;         // X0 pad cols 546..575, both buffers
    const int S8  = 512*64 + 64;      // decWp + decbp
    const int S9  = NJ3*G4;           // WpT
    const int TOT = S1+S1b+S2+S3+S4+S5+S6+S6b+S7+S8+S9;
    int i = blockIdx.x * blockDim.x + threadIdx.x;
    for (; i < TOT; i += gridDim.x * blockDim.x) {
        int r = i;
        if (r < S1) {
            int m = r & 2047; int k = 34 + (r >> 11);
            int mp = ((m & 511) << 2) | (m >> 9);
            g_W0[k*G4 + mp] = f16b(Whh0[m*512 + (k-34)]);
            continue;
        }
        r -= S1;
        if (r < S1b) {
            int m = r & 2047; int k = 546 + (r >> 11);
            int mp = ((m & 511) << 2) | (m >> 9);
            g_W0[k*G4 + mp] = 0;
            continue;
        }
        r -= S1b;
        if (r < S2) {
            int m = r & 2047; int k = r >> 11;
            int mp = ((m & 511) << 2) | (m >> 9);
            float v = (k < 512) ? Wih1[m*512 + k] : Whh1[m*512 + (k-512)];
            g_W1[k*G4 + mp] = f16b(v);
            continue;
        }
        r -= S2;
        if (r < S3) {
            int mp = ((r & 511) << 2) | (r >> 9);
            g_bias1[mp] = bih1[r] + bhh1[r]; continue;
        }
        r -= S3;
        if (r < S4) { int b = r/96, j = r - b*96; g_initp[r] = (j < 85) ? init[b*85 + j] : 0.f; continue; }
        r -= S4;
        if (r < S5) { int k = r >> 9;  g_niW1p[r] = (k < 85) ? niW1[r] : 0.f; continue; }
        r -= S5;
        if (r < S6) {
            int b = r/IN_DIM, j = r - b*IN_DIM;
            g_X0[0][b*K0 + j] = f16b(x[(b*FRAMES)*IN_DIM + j]);
            continue;
        }
        r -= S6;
        if (r < S6b) {
            int b = r >> 7, z = r & 127;
            int buf = z >> 6, j = z & 63;
            float v = 0.f;
            if (buf == 0 && j < NJ3) v = init[b*85 + j] - decb[j];   // predc_0 = pred0 - decb
            g_pred[buf][b*64 + j] = v;
            continue;
        }
        r -= S6b;
        if (r < S7) {
            int b = r/60, z = r - b*60;
            int buf = z/30, col = 546 + (z%30);
            g_X0[buf][b*K0 + col] = 0;
            continue;
        }
        r -= S7;
        if (r < 512*64 + 64) {
            if (r < 512*64) { int k = r >> 6, j = r & 63; g_decWp[r] = (j < NJ3) ? decW[k*NJ3 + j] : 0.f; }
            else { int j = r - 512*64; g_decbp[j] = (j < NJ3) ? decb[j] : 0.f; }
            continue;
        }
        r -= S8;
        {   // WpT[j][mp] = Wih0[m][512+j]
            int m = r & 2047, j = r >> 11;
            int mp = ((m & 511) << 2) | (m >> 9);
            g_WpT[j*G4 + mp] = Wih0[m*563 + 512 + j];
        }
    }
}

// ---------------- generic tiled GEMM (init MLP only; fp32 scalar) -----------
template<bool RELU>
__device__ __forceinline__ void gemm_nt(const float* __restrict__ A, int lda,
                                        const float* __restrict__ B, int ldb,
                                        float* __restrict__ C, int ldc,
                                        int M, int N, int K,
                                        const float* __restrict__ bias,
                                        float* sm) {
    float* As = sm;             // [16][68]
    float* Bs = sm + 16*68;     // [16][64]
    const int tid = threadIdx.x;
    const int nT = N >> 6;
    const int ntiles = (M >> 6) * nT;
    const int ar = tid >> 2, ac = (tid & 3) << 2;
    const int bk = tid >> 4, bn = (tid & 15) << 2;
    const int ty = tid >> 4, tx = tid & 15;
    for (int tile = blockIdx.x; tile < ntiles; tile += gridDim.x) {
        const int m0 = (tile / nT) << 6;
        const int n0 = (tile - (tile / nT) * nT) << 6;
        float4 acc0 = make_float4(0,0,0,0), acc1 = acc0, acc2 = acc0, acc3 = acc0;
        for (int k0 = 0; k0 < K; k0 += 16) {
            float4 va = __ldcg((const float4*)(A + (m0 + ar)*lda + k0 + ac));
            float4 vb = __ldg ((const float4*)(B + (k0 + bk)*ldb + n0 + bn));
            As[(ac+0)*68 + ar] = va.x;
            As[(ac+1)*68 + ar] = va.y;
            As[(ac+2)*68 + ar] = va.z;
            As[(ac+3)*68 + ar] = va.w;
            *(float4*)(Bs + bk*64 + bn) = vb;
            __syncthreads();
            #pragma unroll
            for (int kk = 0; kk < 16; kk++) {
                float4 a = *(const float4*)(As + kk*68 + (ty << 2));
                float4 b = *(const float4*)(Bs + kk*64 + (tx << 2));
                acc0.x += a.x*b.x; acc0.y += a.x*b.y; acc0.z += a.x*b.z; acc0.w += a.x*b.w;
                acc1.x += a.y*b.x; acc1.y += a.y*b.y; acc1.z += a.y*b.z; acc1.w += a.y*b.w;
                acc2.x += a.z*b.x; acc2.y += a.z*b.y; acc2.z += a.z*b.z; acc2.w += a.z*b.w;
                acc3.x += a.w*b.x; acc3.y += a.w*b.y; acc3.z += a.w*b.z; acc3.w += a.w*b.w;
            }
            __syncthreads();
        }
        float4 bb = __ldg((const float4*)(bias + n0 + (tx << 2)));
        float4 accs[4] = {acc0, acc1, acc2, acc3};
        #pragma unroll
        for (int i = 0; i < 4; i++) {
            float4 v = accs[i];
            v.x += bb.x; v.y += bb.y; v.z += bb.z; v.w += bb.w;
            if (RELU) { v.x = fmaxf(v.x, 0.f); v.y = fmaxf(v.y, 0.f);
                        v.z = fmaxf(v.z, 0.f); v.w = fmaxf(v.w, 0.f); }
            __stcg((float4*)(C + (m0 + (ty << 2) + i)*ldc + n0 + (tx << 2)), v);
        }
    }
}

// ---------------- fused fp16 MMA GEMM + LSTM-cell epilogue (4-stage cp.async) ---------
// gates = A @ W, single fp16 operands, fp32 accumulate. 4 MMAs per k16 chunk per warp.
// 64x64 tile per CTA, 8 warps as 2(m) x 4(n), warp tile 32x16.
// Stage (halves): A[64][24] @0, W[16][72] @1536.
template<int LAYER>
__device__ __forceinline__ void gemm_cell_mma(
    const ushort_t* __restrict__ A, int K,
    const ushort_t* __restrict__ W,
    const float* __restrict__ bias,
    float* __restrict__ cArr,
    ushort_t* __restrict__ X0n,                            // X0next
    ushort_t* __restrict__ X1a,                            // layer0: X1cur; layer1: X1next
    const float* __restrict__ predCur, float* __restrict__ predNxt,
    float* __restrict__ out_mc, int t,
    ushort_t* sm)
{
    const int tid = threadIdx.x;
    const int l = tid & 31, w = tid >> 5;
    const int wm = w >> 2, wn = w & 3;
    const int m0 = (blockIdx.x >> 5) << 6;
    const int n0 = (blockIdx.x & 31) << 6;

    // cp.async staging: 1 x 16B per thread (threads 0..127: A tile; 128..255: W tile)
    const int isA = (tid < 128);
    const int u = tid & 127;
    const int a_r = u >> 1, a_c = (u & 1) << 3;            // A: 64 rows x 2 col-groups
    const int w_r = u >> 3, w_c = (u & 7) << 3;            // W: 16 rows x 8 col-groups
    const unsigned int my_dst = isA ? (unsigned)((a_r*24 + a_c)*2)
                                    : (unsigned)((1536 + w_r*72 + w_c)*2);
    const ushort_t* my_src = isA ? (A + (long)(m0 + a_r)*K + a_c)
                                 : (W + (long)w_r*G4 + n0 + w_c);
    const long my_stride = isA ? 16 : (long)16*G4;         // per-chunk src advance

    const unsigned int smb = (unsigned int)__cvta_generic_to_shared(sm);

    float D[2][2][4];
    #pragma unroll
    for (int a = 0; a < 2; a++)
        #pragma unroll
        for (int b = 0; b < 2; b++)
            #pragma unroll
            for (int k = 0; k < 4; k++) D[a][b][k] = 0.f;

    const int NC = K >> 4;

    // prologue: issue chunks 0..2
    #pragma unroll
    for (int s = 0; s < 3; s++) {
        CP_ASYNC16(smb + s*STG_BYTES + my_dst, my_src + s*my_stride);
        CP_COMMIT();
    }

    // lane addresses for LDSM (byte offsets within a stage)
    const unsigned int a_off = wm*1536 + (l & 15)*48 + (l >> 4)*16;
    const unsigned int b_off = 3072 + ((l & 7) + ((l >> 3) & 1)*8)*144
                             + (wn*16 + (l >> 4)*8)*2;

    for (int kc = 0; kc < NC; kc++) {
        CP_WAIT2();
        __syncthreads();
        if (kc + 3 < NC) {
            CP_ASYNC16(smb + ((kc + 3) & 3)*STG_BYTES + my_dst, my_src + (long)(kc + 3)*my_stride);
        }
        CP_COMMIT();

        const unsigned int bb = smb + (kc & 3)*STG_BYTES;
        unsigned int ah0[4], ah1[4], bh[4];
        LDSM4 (ah0, bb + a_off);
        LDSM4 (ah1, bb + a_off + 768);
        LDSM4T(bh,  bb + b_off);
        MMA_F16(D[0][0], ah0, bh[0], bh[1]); MMA_F16(D[0][1], ah0, bh[2], bh[3]);
        MMA_F16(D[1][0], ah1, bh[0], bh[1]); MMA_F16(D[1][1], ah1, bh[2], bh[3]);
    }

    // ---- epilogue ----
    const int tig = l & 3, r = l >> 2;
    const int nw = n0 + wn*16;
    const int mw = m0 + wm*32;
    const int nf0dd = (nw >> 2);

    float* smf = (float*)sm;
    float4 corr[2][2];
    #pragma unroll
    for (int a2 = 0; a2 < 2; a2++)
        #pragma unroll
        for (int b2 = 0; b2 < 2; b2++) corr[a2][b2] = make_float4(0,0,0,0);

    const int ddl_t = (wn*4) + (tig & 1)*2 + (tig >> 1);   // local dd 0..15

    if (LAYER == 0) {
        // stage pred tile [64][52] + Wp slice [51][64]; zero predNxt (n-tile-0 CTA)
        __syncthreads();
        float* preds = smf;              // 64*52
        float* wps   = smf + 64*52;      // 51*64
        for (int i = tid; i < 64*52; i += THREADS) {
            int b2 = i/52, j = i - b2*52;
            preds[i] = (j < NJ3) ? __ldcg(&predCur[(m0 + b2)*64 + j]) : 0.f;
        }
        for (int i = tid; i < NJ3*64; i += THREADS)
            wps[i] = __ldg(&g_WpT[(i >> 6)*G4 + n0 + (i & 63)]);
        if ((blockIdx.x & 31) == 0)
            for (int i = tid; i < 64*64; i += THREADS)
                __stcg(&predNxt[(m0 + (i >> 6))*64 + (i & 63)], 0.f);
        __syncthreads();
        for (int j = 0; j < NJ3; j++) {
            float4 w4 = *(const float4*)(wps + j*64 + 4*ddl_t);
            #pragma unroll
            for (int mf = 0; mf < 2; mf++)
                #pragma unroll
                for (int rr = 0; rr < 2; rr++) {
                    float p = preds[(wm*32 + mf*16 + r + rr*8)*52 + j];
                    corr[mf][rr].x += p*w4.x; corr[mf][rr].y += p*w4.y;
                    corr[mf][rr].z += p*w4.z; corr[mf][rr].w += p*w4.w;
                }
        }
    }

    float* hs = smf;                 // [64][17]  (LAYER 1)
    float* ds = smf + 64*17;         // [16][52]
    if (LAYER == 1) {
        __syncthreads();
        for (int i = tid; i < 16*52; i += THREADS) {
            int dl = i/52, j = i - dl*52;
            ds[i] = (j < NJ3) ? __ldg(&g_decWp[((n0 >> 2) + dl)*64 + j]) : 0.f;
        }
        __syncthreads();
    }

    // LSTM cell on (i,f,g,o) quads via pair shuffle
    #pragma unroll
    for (int mf = 0; mf < 2; mf++) {
        float oth[4];
        #pragma unroll
        for (int k = 0; k < 4; k++) {
            float send = (tig & 1) ? D[mf][0][k] : D[mf][1][k];
            oth[k] = __shfl_xor_sync(0xffffffffu, send, 1);
        }
        const int nf = (tig & 1);
        const int dd = nf0dd + nf*2 + (tig >> 1);
        const float4 bb4 = __ldg((const float4*)(bias + 4*dd));
        float iv[2], fv[2], gv[2], ov[2];
        if (!nf) {
            iv[0] = D[mf][0][0]; fv[0] = D[mf][0][1]; gv[0] = oth[0]; ov[0] = oth[1];
            iv[1] = D[mf][0][2]; fv[1] = D[mf][0][3]; gv[1] = oth[2]; ov[1] = oth[3];
        } else {
            iv[0] = oth[0]; fv[0] = oth[1]; gv[0] = D[mf][1][0]; ov[0] = D[mf][1][1];
            iv[1] = oth[2]; fv[1] = oth[3]; gv[1] = D[mf][1][2]; ov[1] = D[mf][1][3];
        }
        #pragma unroll
        for (int rr = 0; rr < 2; rr++) {
            const int b = mw + mf*16 + r + rr*8;
            float ig = sigf (iv[rr] + bb4.x + corr[mf][rr].x);
            float fg = sigf (fv[rr] + bb4.y + corr[mf][rr].y);
            float gg = tanhg(gv[rr] + bb4.z + corr[mf][rr].z);
            float og = sigf (ov[rr] + bb4.w + corr[mf][rr].w);
            float c  = fg * cArr[b*DDIM + dd] + ig * gg;   // CTA-private
            cArr[b*DDIM + dd] = c;
            float h = og * tanhg(c);
            ushort_t hb = f16b(h);
            if (LAYER == 0) {
                st_cg_u16(&X1a[b*K1 + dd], hb);            // gates1 input (this step)
                st_cg_u16(&X0n[b*K0 + 34 + dd], hb);       // recurrent h0 (next step)
            } else {
                st_cg_u16(&X1a[b*K1 + 512 + dd], hb);      // recurrent h1 (next step)
                out_mc[((long)b*FRAMES + t)*563 + dd] = h; // motion_context h part (fp32)
                hs[(b - m0)*17 + (dd - (n0 >> 2))] = h;    // for pred partials
            }
        }
    }

    if (LAYER == 1) {
        // pred partials: h1_tile @ decW_slice -> atomicAdd into predNxt
        __syncthreads();
        for (int i = tid; i < 64*NJ3; i += THREADS) {
            int lb = i/NJ3, j = i - lb*NJ3;
            float s = 0.f;
            #pragma unroll
            for (int dl = 0; dl < 16; dl++) s += hs[lb*17 + dl] * ds[dl*52 + j];
            atomicAdd(&predNxt[(m0 + lb)*64 + j], s);
        }
    }
}

// ---------------- persistent scan kernel ----------------
__global__ void __launch_bounds__(THREADS, 1)
k_persist(const float* __restrict__ x,
          const float* __restrict__ niW2, const float* __restrict__ niW3,
          const float* __restrict__ nb1,  const float* __restrict__ nb2,
          const float* __restrict__ nb3,
          float* __restrict__ out_mc) {
    __shared__ __align__(16) ushort_t smem[4*STG_HALVES + 4096];   // stages + epilogue scratch
    float* smf = (float*)smem;
    const int gtid = blockIdx.x * THREADS + threadIdx.x;
    const int grp = blockIdx.x >> 5;

    // ---- init network (fp32 scalar path; runs once; global barriers) ----
    gemm_nt<true >(g_initp, 96,   g_niW1p, DDIM, g_z1, DDIM, BATCH, DDIM, 96,   nb1, smf);
    grid_sync();
    gemm_nt<true >(g_z1,   DDIM,  niW2,    1024, g_z2, 1024, BATCH, 1024, DDIM, nb2, smf);
    grid_sync();
    gemm_nt<false>(g_z2,   1024,  niW3,    2048, g_z3, 2048, BATCH, 2048, 1024, nb3, smf);
    grid_sync();
    for (int idx = gtid; idx < BATCH*DDIM; idx += NT) {
        int b = idx >> 9, d = idx & 511;
        const float* zr = g_z3 + b*2048;
        st_cg_u16(&g_X0[0][b*K0 + 34 + d],  f16b(__ldcg(zr + d)));        // h0 init
        st_cg_u16(&g_X1[0][b*K1 + 512 + d], f16b(__ldcg(zr + 512 + d)));  // h1 init
        __stcg(&g_c0[idx], __ldcg(zr + 1024 + d));
        __stcg(&g_c1[idx], __ldcg(zr + 1536 + d));
    }
    grid_sync();

    // ---- scan: 2 group syncs per step (batch dim partitions into 4 groups) ----
    for (int t = 0; t < FRAMES; t++) {
        const int cur = t & 1, nxt = cur ^ 1;

        // phase A: gates0 fp16 MMA GEMM (K=576) + pred@Wp correction + cell0 epilogue
        gemm_cell_mma<0>(g_X0[cur], K0, g_W0, g_bias0, g_c0,
                         g_X0[nxt], g_X1[cur],
                         g_pred[cur], g_pred[nxt], nullptr, t, smem);
        group_sync(grp);

        // phase B: gates1 fp16 MMA GEMM (K=1024) + cell1 epilogue + pred partials
        gemm_cell_mma<1>(g_X1[cur], K1, g_W1, g_bias1, g_c1,
                         nullptr, g_X1[nxt],
                         nullptr, g_pred[nxt], out_mc, t, smem);

        // x_{t+1} copy (one CTA per group; 64 rows)
        if ((blockIdx.x & 31) == 0 && t + 1 < FRAMES) {
            const int mbase = grp << 6;
            for (int i = threadIdx.x; i < 64*IN_DIM; i += THREADS) {
                int rr = i / IN_DIM, j = i - rr*IN_DIM;
                int b = mbase + rr;
                st_cg_u16(&g_X0[nxt][b*K0 + j],
                          f16b(__ldg(&x[((long)b*FRAMES + t + 1)*IN_DIM + j])));
            }
        }
        group_sync(grp);
    }
}

// ---------------- post-scan decoder: preds = H1_all @ decW + decb ----------------
__global__ void __launch_bounds__(256)
k_decode(const float* __restrict__ mc_h,   // out_mc (h part, cols 0..511, stride 563)
         float* __restrict__ out_pred, float* __restrict__ out_mc) {
    __shared__ float As[16*68];
    __shared__ float Bs[16*64];
    const int tid = threadIdx.x;
    const int m0 = blockIdx.x << 6;       // 1024 blocks cover 65536 bt rows
    const int ar = tid >> 2, ac = (tid & 3) << 2;
    const int bk = tid >> 4, bn = (tid & 15) << 2;
    const int ty = tid >> 4, tx = tid & 15;
    float4 acc0 = make_float4(0,0,0,0), acc1 = acc0, acc2 = acc0, acc3 = acc0;
    const long arow = (long)(m0 + ar)*563;
    for (int k0 = 0; k0 < 512; k0 += 16) {
        As[(ac+0)*68 + ar] = __ldg(&mc_h[arow + k0 + ac + 0]);
        As[(ac+1)*68 + ar] = __ldg(&mc_h[arow + k0 + ac + 1]);
        As[(ac+2)*68 + ar] = __ldg(&mc_h[arow + k0 + ac + 2]);
        As[(ac+3)*68 + ar] = __ldg(&mc_h[arow + k0 + ac + 3]);
        *(float4*)(Bs + bk*64 + bn) = *(const float4*)(g_decWp + (k0 + bk)*64 + bn);
        __syncthreads();
        #pragma unroll
        for (int kk = 0; kk < 16; kk++) {
            float4 a = *(const float4*)(As + kk*68 + (ty << 2));
            float4 b = *(const float4*)(Bs + kk*64 + (tx << 2));
            acc0.x += a.x*b.x; acc0.y += a.x*b.y; acc0.z += a.x*b.z; acc0.w += a.x*b.w;
            acc1.x += a.y*b.x; acc1.y += a.y*b.y; acc1.z += a.y*b.z; acc1.w += a.y*b.w;
            acc2.x += a.z*b.x; acc2.y += a.z*b.y; acc2.z += a.z*b.z; acc2.w += a.z*b.w;
            acc3.x += a.w*b.x; acc3.y += a.w*b.y; acc3.z += a.w*b.z; acc3.w += a.w*b.w;
        }
        __syncthreads();
    }
    float4 accs[4] = {acc0, acc1, acc2, acc3};
    #pragma unroll
    for (int i = 0; i < 4; i++) {
        const long bt = m0 + (ty << 2) + i;
        #pragma unroll
        for (int j = 0; j < 4; j++) {
            int col = (tx << 2) + j;
            if (col < NJ3) {
                float v = ((j==0)?accs[i].x:(j==1)?accs[i].y:(j==2)?accs[i].z:accs[i].w)
                        + g_decbp[col];
                out_pred[bt*NJ3 + col] = v;
                out_mc[bt*563 + 512 + col] = v;
            }
        }
    }
}

// ---------------- entry ----------------
extern "C" void kernel_launch(void* const* d_in, const int* in_sizes, int n_in,
                              void* d_out, int out_size) {
    const float* x       = (const float*)d_in[0];
    const float* init_   = (const float*)d_in[1];
    const float* embed_W = (const float*)d_in[2];
    const float* embed_b = (const float*)d_in[3];
    const float* ni_W1   = (const float*)d_in[4];
    const float* ni_b1   = (const float*)d_in[5];
    const float* ni_W2   = (const float*)d_in[6];
    const float* ni_b2   = (const float*)d_in[7];
    const float* ni_W3   = (const float*)d_in[8];
    const float* ni_b3   = (const float*)d_in[9];
    const float* Wih0    = (const float*)d_in[10];
    const float* Whh0    = (const float*)d_in[11];
    const float* bih0    = (const float*)d_in[12];
    const float* bhh0    = (const float*)d_in[13];
    const float* Wih1    = (const float*)d_in[14];
    const float* Whh1    = (const float*)d_in[15];
    const float* bih1    = (const float*)d_in[16];
    const float* bhh1    = (const float*)d_in[17];
    const float* dec_W   = (const float*)d_in[18];
    const float* dec_b   = (const float*)d_in[19];

    float* out_pred = (float*)d_out;                              // (256,256,17,3)
    float* out_mc   = out_pred + (long)BATCH*FRAMES*NJ3;          // (256,256,563)

    k_setup_heavy<<<280, 256>>>(embed_W, embed_b, Wih0, bih0, bhh0, dec_b);
    k_setup_copy <<<2048, 256>>>(x, init_, Wih0, Whh0, Wih1, Whh1, bih1, bhh1, ni_W1,
                                 dec_W, dec_b);
    k_persist    <<<GRID, THREADS>>>(x, ni_W2, ni_W3, ni_b1, ni_b2, ni_b3, out_mc);
    k_decode     <<<1024, 256>>>(out_mc, out_pred, out_mc);
}